// round 12
// baseline (speedup 1.0000x reference)
#include <cuda_runtime.h>
#include <cuda_bf16.h>
#include <cstdint>
#include <cstddef>

// ---------------------------------------------------------------------------
// MHA: B=2, S=2048, E=1024, H=16, D=64, fp32, causal.
//  quant(x), quant(wqkv) -> 2-level int8 (h + l/256, per-row scale)
//  gemm1 (int8 IMMA m16n8k32, 3-term, fused epi): Q'/K'/V' [hi|lo] bf16
//  attn (round-10: BR=128, double-buffered, fragment-reuse) -> E' [hi|lo|hi]
//  split3(w0) ; gemm2 (bf16 3-term mma) -> fp32 out
// ---------------------------------------------------------------------------

#define S_LEN   2048
#define E_DIM   1024
#define K3      3072

__device__ __nv_bfloat16 g_a2[4096 * K3];            // E' [hi|lo|hi]
__device__ __nv_bfloat16 g_w2[1024 * K3];            // W0'
__device__ __nv_bfloat16 g_q [32 * 2048 * 128];      // Q' [hi|lo]
__device__ __nv_bfloat16 g_k [32 * 2048 * 128];      // K' [hi|lo]
__device__ __nv_bfloat16 g_v [32 * 2048 * 128];      // V' [hi|lo]
__device__ int8_t g_xq[4096 * 2048];                 // X int8 [h(1024)|l(1024)]
__device__ int8_t g_wq[3072 * 2048];                 // Wqkv int8
__device__ float  g_sx[4096];
__device__ float  g_sw[3072];

// ---------------------------------------------------------------------------
__device__ __forceinline__ uint32_t smem_u32(const void* p) {
    uint32_t a;
    asm("{ .reg .u64 t; cvta.to.shared.u64 t, %1; cvt.u32.u64 %0, t; }"
        : "=r"(a) : "l"(p));
    return a;
}
__device__ __forceinline__ uint32_t pk(__nv_bfloat16 a, __nv_bfloat16 b) {
    __nv_bfloat162 t = __halves2bfloat162(a, b);
    return *reinterpret_cast<uint32_t*>(&t);
}
__device__ __forceinline__ uint32_t pkf(float a, float b) {
    return pk(__float2bfloat16(a), __float2bfloat16(b));
}
__device__ __forceinline__ void ldsm4(uint32_t r[4], uint32_t addr) {
    asm volatile("ldmatrix.sync.aligned.m8n8.x4.shared.b16 {%0,%1,%2,%3}, [%4];"
                 : "=r"(r[0]), "=r"(r[1]), "=r"(r[2]), "=r"(r[3]) : "r"(addr));
}
__device__ __forceinline__ void ldsm4t(uint32_t r[4], uint32_t addr) {
    asm volatile("ldmatrix.sync.aligned.m8n8.x4.trans.shared.b16 {%0,%1,%2,%3}, [%4];"
                 : "=r"(r[0]), "=r"(r[1]), "=r"(r[2]), "=r"(r[3]) : "r"(addr));
}
__device__ __forceinline__ void mma16816(float c[4], const uint32_t a[4],
                                         uint32_t b0, uint32_t b1) {
    asm volatile("mma.sync.aligned.m16n8k16.row.col.f32.bf16.bf16.f32 "
                 "{%0,%1,%2,%3}, {%4,%5,%6,%7}, {%8,%9}, {%0,%1,%2,%3};"
                 : "+f"(c[0]), "+f"(c[1]), "+f"(c[2]), "+f"(c[3])
                 : "r"(a[0]), "r"(a[1]), "r"(a[2]), "r"(a[3]), "r"(b0), "r"(b1));
}
__device__ __forceinline__ void mma_s8(int32_t c[4], const uint32_t a[4],
                                       uint32_t b0, uint32_t b1) {
    asm volatile("mma.sync.aligned.m16n8k32.row.col.s32.s8.s8.s32 "
                 "{%0,%1,%2,%3}, {%4,%5,%6,%7}, {%8,%9}, {%0,%1,%2,%3};"
                 : "+r"(c[0]), "+r"(c[1]), "+r"(c[2]), "+r"(c[3])
                 : "r"(a[0]), "r"(a[1]), "r"(a[2]), "r"(a[3]), "r"(b0), "r"(b1));
}
__device__ __forceinline__ void cpa16(uint32_t dst, const void* src) {
    asm volatile("cp.async.cg.shared.global [%0], [%1], 16;" :: "r"(dst), "l"(src));
}

// ---------------------------------------------------------------------------
// quant: fp32 [rows,1024] -> int8 [rows, 2048] planar [h|l], x = s*(h + l/256)
// one warp per row.
// ---------------------------------------------------------------------------
__global__ void quant_kernel(const float* __restrict__ src,
                             int8_t* __restrict__ dst,
                             float* __restrict__ scales, int rows) {
    int r = blockIdx.x * 8 + (threadIdx.x >> 5);
    if (r >= rows) return;
    int lane = threadIdx.x & 31;
    const float4* s4 = (const float4*)(src + (size_t)r * 1024);
    float4 v[8];
    float mx = 0.0f;
#pragma unroll
    for (int j = 0; j < 8; ++j) {
        v[j] = s4[j * 32 + lane];
        mx = fmaxf(mx, fmaxf(fmaxf(fabsf(v[j].x), fabsf(v[j].y)),
                             fmaxf(fabsf(v[j].z), fabsf(v[j].w))));
    }
#pragma unroll
    for (int off = 16; off >= 1; off >>= 1)
        mx = fmaxf(mx, __shfl_xor_sync(0xffffffffu, mx, off));
    float s1 = fmaxf(mx * (1.0f / 127.0f), 1e-30f);
    float inv1 = 1.0f / s1;
    float inv2 = 256.0f / s1;
    if (lane == 0) scales[r] = s1;
    int8_t* dh = dst + (size_t)r * 2048;
    int8_t* dl = dh + 1024;
#pragma unroll
    for (int j = 0; j < 8; ++j) {
        float f[4] = {v[j].x, v[j].y, v[j].z, v[j].w};
        uint32_t hp = 0, lp = 0;
#pragma unroll
        for (int e = 0; e < 4; ++e) {
            int hi = __float2int_rn(f[e] * inv1);
            hi = max(-127, min(127, hi));
            float res = f[e] - (float)hi * s1;
            int lo = __float2int_rn(res * inv2);
            lo = max(-127, min(127, lo));
            hp |= (uint32_t)(uint8_t)(int8_t)hi << (e * 8);
            lp |= (uint32_t)(uint8_t)(int8_t)lo << (e * 8);
        }
        *(uint32_t*)(dh + (j * 32 + lane) * 4) = hp;
        *(uint32_t*)(dl + (j * 32 + lane) * 4) = lp;
    }
}

// ---------------------------------------------------------------------------
// split3: fp32 [rows,K] -> bf16 [rows,3K]. loblk 1: [hi|lo|hi]; 2: [hi|hi|lo]
// ---------------------------------------------------------------------------
__global__ void split3_kernel(const float* __restrict__ src,
                              __nv_bfloat16* __restrict__ dst,
                              int rows, int K, int loblk) {
    int t = blockIdx.x * blockDim.x + threadIdx.x;
    int per4 = K >> 2;
    if (t >= rows * per4) return;
    int r = t / per4, c4 = (t - r * per4) * 4;
    float4 v = ((const float4*)src)[t];

    __nv_bfloat16 h0 = __float2bfloat16(v.x), h1 = __float2bfloat16(v.y);
    __nv_bfloat16 h2 = __float2bfloat16(v.z), h3 = __float2bfloat16(v.w);
    uint2 hp = make_uint2(pk(h0, h1), pk(h2, h3));
    uint2 lp = make_uint2(pkf(v.x - __bfloat162float(h0), v.y - __bfloat162float(h1)),
                          pkf(v.z - __bfloat162float(h2), v.w - __bfloat162float(h3)));

    __nv_bfloat16* d0 = dst + (size_t)r * (3 * K) + c4;
    *(uint2*)(d0)         = hp;
    *(uint2*)(d0 + K)     = (loblk == 1) ? lp : hp;
    *(uint2*)(d0 + 2 * K) = (loblk == 1) ? hp : lp;
}

extern __shared__ char sh_raw[];

// ---------------------------------------------------------------------------
// int8 GEMM (gemm1): C = Xq @ Wq^T with 3-term 2-level int8, fused QKV
// bf16-split epilogue. Tile 128x128, 256 thr, 3-stage cp.async, 1 CTA/SM.
// Per iteration: 64 k-bytes per plane (2 x k32 slices).
// ---------------------------------------------------------------------------
#define IS_TROW 80                      // bytes per smem row (64 data + 16 pad)
#define IS_TILE (128 * IS_TROW)         // 10240
#define IS_STAGE (4 * IS_TILE)          // 40960: Ah, Al, Bh, Bl
#define IGEMM_SMEM (3 * IS_STAGE)       // 122880

__global__ __launch_bounds__(256)
void gemm_s8_qkv(const int8_t* __restrict__ Aq, const int8_t* __restrict__ Bq,
                 const float* __restrict__ sA, const float* __restrict__ sB,
                 __nv_bfloat16* __restrict__ Qd,
                 __nv_bfloat16* __restrict__ Kd,
                 __nv_bfloat16* __restrict__ Vd) {
    const uint32_t sb = smem_u32(sh_raw);
    const int tid = threadIdx.x, wid = tid >> 5, lane = tid & 31;
    const int bm = blockIdx.y * 128, bn = blockIdx.x * 128;
    const int wm = (wid >> 2) * 64, wn = (wid & 3) * 32;
    const int g = lane >> 2, tg = lane & 3;
    const int lrow = lane & 15, lcol = (lane >> 4) * 8;   // lcol in byte-pairs

    auto load_stage = [&](int s, int gk) {
        uint32_t base = sb + (uint32_t)s * IS_STAGE;
        const int koff = gk * 64;
#pragma unroll
        for (int i = 0; i < 8; ++i) {
            int c = tid + i * 256;
            int tile = c >> 9, cc = c & 511;
            int row = cc >> 2, ch = cc & 3;
            const int8_t* gsrc;
            if (tile == 0)      gsrc = Aq + (size_t)(bm + row) * 2048 + koff + ch * 16;
            else if (tile == 1) gsrc = Aq + (size_t)(bm + row) * 2048 + 1024 + koff + ch * 16;
            else if (tile == 2) gsrc = Bq + (size_t)(bn + row) * 2048 + koff + ch * 16;
            else                gsrc = Bq + (size_t)(bn + row) * 2048 + 1024 + koff + ch * 16;
            cpa16(base + tile * IS_TILE + row * IS_TROW + ch * 16, gsrc);
        }
        asm volatile("cp.async.commit_group;" ::: "memory");
    };

    int32_t accA[4][4][4], accX[4][4][4];
#pragma unroll
    for (int i = 0; i < 4; ++i)
#pragma unroll
        for (int j = 0; j < 4; ++j)
#pragma unroll
            for (int e = 0; e < 4; ++e) { accA[i][j][e] = 0; accX[i][j][e] = 0; }

    const int NC = 16;   // 1024 bytes / 64 per iteration
    load_stage(0, 0);
    load_stage(1, 1);

    int st = 0;
    for (int c = 0; c < NC; ++c) {
        if (c + 1 < NC) asm volatile("cp.async.wait_group 1;" ::: "memory");
        else            asm volatile("cp.async.wait_group 0;" ::: "memory");
        __syncthreads();
        if (c + 2 < NC) {
            int ns = st + 2; if (ns >= 3) ns -= 3;
            load_stage(ns, c + 2);
        }

        uint32_t ahb = sb + (uint32_t)st * IS_STAGE;
        uint32_t alb = ahb + IS_TILE;
        uint32_t bhb = ahb + 2 * IS_TILE;
        uint32_t blb = ahb + 3 * IS_TILE;

#pragma unroll
        for (int sl = 0; sl < 2; ++sl) {        // two k32 slices (32 B each)
            const uint32_t cofs = (uint32_t)(sl * 16 + lcol) * 2;  // byte offset
            uint32_t ah[4][4];
#pragma unroll
            for (int mt = 0; mt < 4; ++mt)
                ldsm4(ah[mt], ahb + (wm + mt * 16 + lrow) * IS_TROW + cofs);
            uint32_t bh[4][2];
#pragma unroll
            for (int nb = 0; nb < 2; ++nb) {
                uint32_t r[4];
                ldsm4(r, bhb + (wn + nb * 16 + lrow) * IS_TROW + cofs);
                bh[nb * 2][0] = r[0];     bh[nb * 2][1] = r[2];
                bh[nb * 2 + 1][0] = r[1]; bh[nb * 2 + 1][1] = r[3];
            }
#pragma unroll
            for (int mt = 0; mt < 4; ++mt)
#pragma unroll
                for (int nt = 0; nt < 4; ++nt)
                    mma_s8(accA[mt][nt], ah[mt], bh[nt][0], bh[nt][1]);

            uint32_t al[4][4];
#pragma unroll
            for (int mt = 0; mt < 4; ++mt)
                ldsm4(al[mt], alb + (wm + mt * 16 + lrow) * IS_TROW + cofs);
#pragma unroll
            for (int mt = 0; mt < 4; ++mt)
#pragma unroll
                for (int nt = 0; nt < 4; ++nt)
                    mma_s8(accX[mt][nt], al[mt], bh[nt][0], bh[nt][1]);

            uint32_t bl[4][2];
#pragma unroll
            for (int nb = 0; nb < 2; ++nb) {
                uint32_t r[4];
                ldsm4(r, blb + (wn + nb * 16 + lrow) * IS_TROW + cofs);
                bl[nb * 2][0] = r[0];     bl[nb * 2][1] = r[2];
                bl[nb * 2 + 1][0] = r[1]; bl[nb * 2 + 1][1] = r[3];
            }
#pragma unroll
            for (int mt = 0; mt < 4; ++mt)
#pragma unroll
                for (int nt = 0; nt < 4; ++nt)
                    mma_s8(accX[mt][nt], ah[mt], bl[nt][0], bl[nt][1]);
        }
        ++st; if (st >= 3) st = 0;
    }

    // fused QKV split epilogue with dequant: [hi(64)|lo(64)] rows per (b,h)
#pragma unroll
    for (int nt = 0; nt < 4; ++nt) {
        int cbase = bn + wn + nt * 8 + tg * 2;
        int plane = cbase >> 10, rem = cbase & 1023;
        int h = rem >> 6, d = rem & 63;
        __nv_bfloat16* basep = (plane == 0) ? Qd : (plane == 1) ? Kd : Vd;
        float sw0 = sB[cbase], sw1 = sB[cbase + 1];
#pragma unroll
        for (int mt = 0; mt < 4; ++mt) {
#pragma unroll
            for (int rr = 0; rr < 2; ++rr) {
                int row = bm + wm + mt * 16 + g + rr * 8;
                int b = row >> 11, s = row & 2047;
                float sr = sA[row];
                float v0 = sr * sw0 * ((float)accA[mt][nt][rr * 2] +
                                       (float)accX[mt][nt][rr * 2] * (1.0f / 256.0f));
                float v1 = sr * sw1 * ((float)accA[mt][nt][rr * 2 + 1] +
                                       (float)accX[mt][nt][rr * 2 + 1] * (1.0f / 256.0f));
                __nv_bfloat16 h0 = __float2bfloat16(v0), h1 = __float2bfloat16(v1);
                uint32_t hi = pk(h0, h1);
                uint32_t lo = pkf(v0 - __bfloat162float(h0), v1 - __bfloat162float(h1));
                __nv_bfloat16* p = basep +
                    ((size_t)(b * 16 + h) * 2048 + s) * 128 + d;
                *(uint32_t*)(p)      = hi;
                *(uint32_t*)(p + 64) = lo;
            }
        }
    }
}

// ---------------------------------------------------------------------------
// bf16 GEMM (gemm2): C = A[M,K] @ B[N,K]^T, fp32 out (round-10 proven).
// ---------------------------------------------------------------------------
#define BM 128
#define BN 128
#define BK 64
#define KSTRB 144
#define STG_BYTES ((BM + BN) * KSTRB)   // 36864
#define GEMM_SMEM (3 * STG_BYTES)       // 110592

__global__ __launch_bounds__(256, 2)
void gemm_mma(const __nv_bfloat16* __restrict__ A,
              const __nv_bfloat16* __restrict__ B,
              float* __restrict__ C, int M, int N, int K) {
    const uint32_t sb = smem_u32(sh_raw);
    const int tid = threadIdx.x, wid = tid >> 5, lane = tid & 31;
    const int bm = blockIdx.y * BM, bn = blockIdx.x * BN;
    const int wm = (wid >> 2) * 64, wn = (wid & 3) * 32;
    const int g = lane >> 2, tg = lane & 3;
    const int lrow = lane & 15, lcol = (lane >> 4) * 8;

    auto load_stage = [&](int s, int kk) {
        uint32_t abase = sb + (uint32_t)s * STG_BYTES;
        uint32_t bbase = abase + BM * KSTRB;
#pragma unroll
        for (int i = 0; i < 8; ++i) {
            int c = tid + i * 256;
            if (c < 1024) {
                int row = c >> 3, k16 = c & 7;
                cpa16(abase + row * KSTRB + k16 * 16,
                      A + (size_t)(bm + row) * K + kk + k16 * 8);
            } else {
                int row = (c - 1024) >> 3, k16 = c & 7;
                cpa16(bbase + row * KSTRB + k16 * 16,
                      B + (size_t)(bn + row) * K + kk + k16 * 8);
            }
        }
        asm volatile("cp.async.commit_group;" ::: "memory");
    };

    float acc[4][4][4];
#pragma unroll
    for (int i = 0; i < 4; ++i)
#pragma unroll
        for (int j = 0; j < 4; ++j)
#pragma unroll
            for (int e = 0; e < 4; ++e) acc[i][j][e] = 0.0f;

    const int NC = K / BK;
    load_stage(0, 0);
    load_stage(1, BK);

    int st = 0;
    for (int c = 0; c < NC; ++c) {
        if (c + 1 < NC) asm volatile("cp.async.wait_group 1;" ::: "memory");
        else            asm volatile("cp.async.wait_group 0;" ::: "memory");
        __syncthreads();
        if (c + 2 < NC) {
            int ns = st + 2; if (ns >= 3) ns -= 3;
            load_stage(ns, (c + 2) * BK);
        }

        uint32_t abase = sb + (uint32_t)st * STG_BYTES;
        uint32_t bbase = abase + BM * KSTRB;
#pragma unroll
        for (int ks = 0; ks < 4; ++ks) {
            uint32_t a[4][4];
#pragma unroll
            for (int mt = 0; mt < 4; ++mt)
                ldsm4(a[mt], abase + (wm + mt * 16 + lrow) * KSTRB + (ks * 16 + lcol) * 2);
            uint32_t bf[4][2];
#pragma unroll
            for (int nb = 0; nb < 2; ++nb) {
                uint32_t r[4];
                ldsm4(r, bbase + (wn + nb * 16 + lrow) * KSTRB + (ks * 16 + lcol) * 2);
                bf[nb * 2][0] = r[0];     bf[nb * 2][1] = r[2];
                bf[nb * 2 + 1][0] = r[1]; bf[nb * 2 + 1][1] = r[3];
            }
#pragma unroll
            for (int mt = 0; mt < 4; ++mt)
#pragma unroll
                for (int nt = 0; nt < 4; ++nt)
                    mma16816(acc[mt][nt], a[mt], bf[nt][0], bf[nt][1]);
        }
        ++st; if (st >= 3) st = 0;
    }

#pragma unroll
    for (int mt = 0; mt < 4; ++mt) {
        int r0 = bm + wm + mt * 16 + g;
#pragma unroll
        for (int nt = 0; nt < 4; ++nt) {
            int col = bn + wn + nt * 8 + tg * 2;
            *(float2*)(C + (size_t)r0 * N + col) =
                make_float2(acc[mt][nt][0], acc[mt][nt][1]);
            *(float2*)(C + (size_t)(r0 + 8) * N + col) =
                make_float2(acc[mt][nt][2], acc[mt][nt][3]);
        }
    }
}

// ---------------------------------------------------------------------------
// Flash attention (round-10 proven): BR=128, BC=64, 256 thr, paired q-tiles,
// double-buffered K/V, fragment-reuse 3-term QK, exp2 softmax. E' [hi|lo|hi].
// ---------------------------------------------------------------------------
#define STR 136
#define Q_EL  (128 * STR)
#define KV_EL (64 * STR)
#define ATT_SMEM ((Q_EL + 4 * KV_EL) * 2)   // 104448

__global__ __launch_bounds__(256, 2)
void attn_mma5(const __nv_bfloat16* __restrict__ Qg,
               const __nv_bfloat16* __restrict__ Kg,
               const __nv_bfloat16* __restrict__ Vg,
               __nv_bfloat16* __restrict__ Eo) {
    const uint32_t sbQ = smem_u32(sh_raw);

    const int tid = threadIdx.x, wid = tid >> 5, lane = tid & 31;
    const int h = blockIdx.y, b = blockIdx.z;
    const size_t bh = (size_t)(b * 16 + h);
    const int g = lane >> 2, tg = lane & 3;
    const int lrow = lane & 15, lcol = (lane >> 4) * 8;
    const float scale = 0.125f * 1.44269504089f;

    auto load_kv = [&](int buf, int k0) {
        uint32_t kb = sbQ + (Q_EL + buf * 2 * KV_EL) * 2;
        uint32_t vb = kb + KV_EL * 2;
        const __nv_bfloat16* kg = Kg + (bh * 2048 + k0) * 128;
        const __nv_bfloat16* vg = Vg + (bh * 2048 + k0) * 128;
#pragma unroll
        for (int i = 0; i < 4; ++i) {
            int c = tid + i * 256;
            int row = c >> 4, cg = c & 15;
            cpa16(kb + (row * STR + cg * 8) * 2, kg + row * 128 + cg * 8);
            cpa16(vb + (row * STR + cg * 8) * 2, vg + row * 128 + cg * 8);
        }
        asm volatile("cp.async.commit_group;" ::: "memory");
    };

#pragma unroll 1
    for (int ph = 0; ph < 2; ++ph) {
        const int qi = ph ? (int)blockIdx.x : 15 - (int)blockIdx.x;
        const int q0 = qi * 128;
        const int ntiles = 2 * qi + 2;
        const int rowg0 = q0 + wid * 16 + g, rowg1 = rowg0 + 8;

        {
            const __nv_bfloat16* qg = Qg + (bh * 2048 + q0) * 128;
#pragma unroll
            for (int i = 0; i < 8; ++i) {
                int c = tid + i * 256;
                int row = c >> 4, cg = c & 15;
                cpa16(sbQ + (row * STR + cg * 8) * 2, qg + row * 128 + cg * 8);
            }
            asm volatile("cp.async.commit_group;" ::: "memory");
        }
        load_kv(0, 0);

        float m0 = -1e30f, m1 = -1e30f, l0 = 0.0f, l1 = 0.0f;
        float o[8][4];
#pragma unroll
        for (int i = 0; i < 8; ++i)
#pragma unroll
            for (int j = 0; j < 4; ++j) o[i][j] = 0.0f;

        for (int t = 0; t < ntiles; ++t) {
            const int k0 = t * 64;
            asm volatile("cp.async.wait_group 0;" ::: "memory");
            __syncthreads();
            if (t + 1 < ntiles) load_kv((t + 1) & 1, (t + 1) * 64);

            const uint32_t kbase = sbQ + (Q_EL + (t & 1) * 2 * KV_EL) * 2;
            const uint32_t vbase = kbase + KV_EL * 2;

            float s[8][4];
#pragma unroll
            for (int i = 0; i < 8; ++i)
#pragma unroll
                for (int j = 0; j < 4; ++j) s[i][j] = 0.0f;

#pragma unroll
            for (int i = 0; i < 4; ++i) {
                uint32_t qa0[4], qa1[4];
                ldsm4(qa0, sbQ + ((wid * 16 + lrow) * STR + i * 16 + lcol) * 2);
                ldsm4(qa1, sbQ + ((wid * 16 + lrow) * STR + (i + 4) * 16 + lcol) * 2);
#pragma unroll
                for (int nb = 0; nb < 4; ++nb) {
                    uint32_t r0[4], r1[4];
                    ldsm4(r0, kbase + ((nb * 16 + lrow) * STR + i * 16 + lcol) * 2);
                    ldsm4(r1, kbase + ((nb * 16 + lrow) * STR + (i + 4) * 16 + lcol) * 2);
                    mma16816(s[nb * 2],     qa0, r0[0], r0[2]);
                    mma16816(s[nb * 2 + 1], qa0, r0[1], r0[3]);
                    mma16816(s[nb * 2],     qa1, r0[0], r0[2]);
                    mma16816(s[nb * 2 + 1], qa1, r0[1], r0[3]);
                    mma16816(s[nb * 2],     qa0, r1[0], r1[2]);
                    mma16816(s[nb * 2 + 1], qa0, r1[1], r1[3]);
                }
            }

            if (t >= ntiles - 2) {
#pragma unroll
                for (int nt = 0; nt < 8; ++nt)
#pragma unroll
                    for (int ee = 0; ee < 4; ++ee) {
                        int col = k0 + nt * 8 + tg * 2 + (ee & 1);
                        int row = (ee < 2) ? rowg0 : rowg1;
                        if (col > row) s[nt][ee] = -1e30f;
                        else           s[nt][ee] *= scale;
                    }
            } else {
#pragma unroll
                for (int nt = 0; nt < 8; ++nt)
#pragma unroll
                    for (int ee = 0; ee < 4; ++ee) s[nt][ee] *= scale;
            }

            float rmax0 = -1e30f, rmax1 = -1e30f;
#pragma unroll
            for (int nt = 0; nt < 8; ++nt) {
                rmax0 = fmaxf(rmax0, fmaxf(s[nt][0], s[nt][1]));
                rmax1 = fmaxf(rmax1, fmaxf(s[nt][2], s[nt][3]));
            }
            rmax0 = fmaxf(rmax0, __shfl_xor_sync(0xffffffffu, rmax0, 1));
            rmax0 = fmaxf(rmax0, __shfl_xor_sync(0xffffffffu, rmax0, 2));
            rmax1 = fmaxf(rmax1, __shfl_xor_sync(0xffffffffu, rmax1, 1));
            rmax1 = fmaxf(rmax1, __shfl_xor_sync(0xffffffffu, rmax1, 2));

            float mn0 = fmaxf(m0, rmax0), mn1 = fmaxf(m1, rmax1);
            float al0 = exp2f(m0 - mn0), al1 = exp2f(m1 - mn1);
            m0 = mn0; m1 = mn1;

            float rs0 = 0.0f, rs1 = 0.0f;
#pragma unroll
            for (int nt = 0; nt < 8; ++nt) {
                s[nt][0] = exp2f(s[nt][0] - m0);
                s[nt][1] = exp2f(s[nt][1] - m0);
                s[nt][2] = exp2f(s[nt][2] - m1);
                s[nt][3] = exp2f(s[nt][3] - m1);
                rs0 += s[nt][0] + s[nt][1];
                rs1 += s[nt][2] + s[nt][3];
            }
            rs0 += __shfl_xor_sync(0xffffffffu, rs0, 1);
            rs0 += __shfl_xor_sync(0xffffffffu, rs0, 2);
            rs1 += __shfl_xor_sync(0xffffffffu, rs1, 1);
            rs1 += __shfl_xor_sync(0xffffffffu, rs1, 2);
            l0 = l0 * al0 + rs0;
            l1 = l1 * al1 + rs1;
#pragma unroll
            for (int nt = 0; nt < 8; ++nt) {
                o[nt][0] *= al0; o[nt][1] *= al0;
                o[nt][2] *= al1; o[nt][3] *= al1;
            }

            uint32_t pfh[4][4], pfl[4][4];
#pragma unroll
            for (int kc = 0; kc < 4; ++kc) {
                const float* se = s[kc * 2];
                const float* so = s[kc * 2 + 1];
                __nv_bfloat16 he0 = __float2bfloat16(se[0]), he1 = __float2bfloat16(se[1]);
                __nv_bfloat16 he2 = __float2bfloat16(se[2]), he3 = __float2bfloat16(se[3]);
                __nv_bfloat16 ho0 = __float2bfloat16(so[0]), ho1 = __float2bfloat16(so[1]);
                __nv_bfloat16 ho2 = __float2bfloat16(so[2]), ho3 = __float2bfloat16(so[3]);
                pfh[kc][0] = pk(he0, he1); pfh[kc][1] = pk(he2, he3);
                pfh[kc][2] = pk(ho0, ho1); pfh[kc][3] = pk(ho2, ho3);
                pfl[kc][0] = pkf(se[0] - __bfloat162float(he0), se[1] - __bfloat162float(he1));
                pfl[kc][1] = pkf(se[2] - __bfloat162float(he2), se[3] - __bfloat162float(he3));
                pfl[kc][2] = pkf(so[0] - __bfloat162float(ho0), so[1] - __bfloat162float(ho1));
                pfl[kc][3] = pkf(so[2] - __bfloat162float(ho2), so[3] - __bfloat162float(ho3));
            }

#pragma unroll
            for (int kc = 0; kc < 4; ++kc) {
#pragma unroll
                for (int db = 0; db < 4; ++db) {
                    uint32_t rh[4];
                    ldsm4t(rh, vbase + ((kc * 16 + lrow) * STR + db * 16 + lcol) * 2);
                    mma16816(o[db * 2],     pfh[kc], rh[0], rh[1]);
                    mma16816(o[db * 2 + 1], pfh[kc], rh[2], rh[3]);
                    mma16816(o[db * 2],     pfl[kc], rh[0], rh[1]);
                    mma16816(o[db * 2 + 1], pfl[kc], rh[2], rh[3]);
                    uint32_t rl[4];
                    ldsm4t(rl, vbase + ((kc * 16 + lrow) * STR + 64 + db * 16 + lcol) * 2);
                    mma16816(o[db * 2],     pfh[kc], rl[0], rl[1]);
                    mma16816(o[db * 2 + 1], pfh[kc], rl[2], rl[3]);
                }
            }
        }

        float inv0 = 1.0f / l0, inv1 = 1.0f / l1;
        size_t r0 = (size_t)(b * 2048) + rowg0;
        size_t r1 = (size_t)(b * 2048) + rowg1;
#pragma unroll
        for (int nt = 0; nt < 8; ++nt) {
            int col = h * 64 + nt * 8 + tg * 2;
            float a0 = o[nt][0] * inv0, a1 = o[nt][1] * inv0;
            float b0 = o[nt][2] * inv1, b1 = o[nt][3] * inv1;
            __nv_bfloat16 ah0 = __float2bfloat16(a0), ah1 = __float2bfloat16(a1);
            __nv_bfloat16 bh0 = __float2bfloat16(b0), bh1 = __float2bfloat16(b1);
            uint32_t ahi = pk(ah0, ah1);
            uint32_t alo = pkf(a0 - __bfloat162float(ah0), a1 - __bfloat162float(ah1));
            uint32_t bhi = pk(bh0, bh1);
            uint32_t blo = pkf(b0 - __bfloat162float(bh0), b1 - __bfloat162float(bh1));
            __nv_bfloat16* p0 = Eo + r0 * K3 + col;
            __nv_bfloat16* p1 = Eo + r1 * K3 + col;
            *(uint32_t*)(p0)        = ahi;
            *(uint32_t*)(p0 + 1024) = alo;
            *(uint32_t*)(p0 + 2048) = ahi;
            *(uint32_t*)(p1)        = bhi;
            *(uint32_t*)(p1 + 1024) = blo;
            *(uint32_t*)(p1 + 2048) = bhi;
        }

        __syncthreads();
    }
}

// ---------------------------------------------------------------------------
// launch
// ---------------------------------------------------------------------------
extern "C" void kernel_launch(void* const* d_in, const int* in_sizes, int n_in,
                              void* d_out, int out_size) {
    (void)in_sizes; (void)n_in; (void)out_size;
    const float* x    = (const float*)d_in[0];
    const float* wqkv = (const float*)d_in[1];
    const float* w0   = (const float*)d_in[2];
    float* out = (float*)d_out;

    __nv_bfloat16 *a2, *w2, *qd, *kd, *vd;
    int8_t *xq, *wq;
    float *sx, *sw;
    cudaGetSymbolAddress((void**)&a2, g_a2);
    cudaGetSymbolAddress((void**)&w2, g_w2);
    cudaGetSymbolAddress((void**)&qd, g_q);
    cudaGetSymbolAddress((void**)&kd, g_k);
    cudaGetSymbolAddress((void**)&vd, g_v);
    cudaGetSymbolAddress((void**)&xq, g_xq);
    cudaGetSymbolAddress((void**)&wq, g_wq);
    cudaGetSymbolAddress((void**)&sx, g_sx);
    cudaGetSymbolAddress((void**)&sw, g_sw);

    cudaFuncSetAttribute(gemm_s8_qkv,
                         cudaFuncAttributeMaxDynamicSharedMemorySize, IGEMM_SMEM);
    cudaFuncSetAttribute(gemm_mma,
                         cudaFuncAttributeMaxDynamicSharedMemorySize, GEMM_SMEM);
    cudaFuncSetAttribute(attn_mma5,
                         cudaFuncAttributeMaxDynamicSharedMemorySize, ATT_SMEM);

    // 1) two-level int8 quantization of X and Wqkv
    quant_kernel<<<4096 / 8, 256>>>(x, xq, sx, 4096);
    quant_kernel<<<3072 / 8, 256>>>(wqkv, wq, sw, 3072);

    // 2) gemm1 (int8 IMMA), fused QKV bf16-split epilogue
    gemm_s8_qkv<<<dim3(24, 32), 256, IGEMM_SMEM>>>(xq, wq, sx, sw, qd, kd, vd);

    // 3) attention -> E' [hi|lo|hi] (into g_a2)
    attn_mma5<<<dim3(8, 16, 2), 256, ATT_SMEM>>>(qd, kd, vd, a2);

    // 4) split W0 and gemm2 (bf16 3-term)
    split3_kernel<<<(E_DIM * E_DIM / 4 + 255) / 256, 256>>>(w0, w2, E_DIM, E_DIM, 2);
    gemm_mma<<<dim3(E_DIM / BN, 4096 / BM), 256, GEMM_SMEM>>>(
        a2, w2, out, 4096, E_DIM, K3);
}

// round 13
// speedup vs baseline: 1.7331x; 1.7331x over previous
#include <cuda_runtime.h>
#include <cuda_bf16.h>
#include <cstdint>
#include <cstddef>

// ---------------------------------------------------------------------------
// MHA: B=2, S=2048, E=1024, H=16, D=64, fp32, causal. mma.sync bf16 split-hi/lo.
//  split3(x)->A', split3(wqkv)->B'
//  gemm1 (128x64 tiles, 4 CTAs/SM, fused epi): Q'/K'/V' [hi|lo] bf16
//  attn (round-10: BR=128, paired q-tiles, double-buffered) -> E' [hi|lo|hi]
//  split3(w0)->B' ; gemm2 (128x128) -> fp32 out
// ---------------------------------------------------------------------------

#define S_LEN   2048
#define E_DIM   1024
#define K3      3072

__device__ __nv_bfloat16 g_a2[4096 * K3];            // X' then E'
__device__ __nv_bfloat16 g_w2[3072 * K3];            // Wqkv' then W0'
__device__ __nv_bfloat16 g_q [32 * 2048 * 128];      // Q' [hi|lo]
__device__ __nv_bfloat16 g_k [32 * 2048 * 128];      // K' [hi|lo]
__device__ __nv_bfloat16 g_v [32 * 2048 * 128];      // V' [hi|lo]

// ---------------------------------------------------------------------------
__device__ __forceinline__ uint32_t smem_u32(const void* p) {
    uint32_t a;
    asm("{ .reg .u64 t; cvta.to.shared.u64 t, %1; cvt.u32.u64 %0, t; }"
        : "=r"(a) : "l"(p));
    return a;
}
__device__ __forceinline__ uint32_t pk(__nv_bfloat16 a, __nv_bfloat16 b) {
    __nv_bfloat162 t = __halves2bfloat162(a, b);
    return *reinterpret_cast<uint32_t*>(&t);
}
__device__ __forceinline__ uint32_t pkf(float a, float b) {
    return pk(__float2bfloat16(a), __float2bfloat16(b));
}
__device__ __forceinline__ void ldsm4(uint32_t r[4], uint32_t addr) {
    asm volatile("ldmatrix.sync.aligned.m8n8.x4.shared.b16 {%0,%1,%2,%3}, [%4];"
                 : "=r"(r[0]), "=r"(r[1]), "=r"(r[2]), "=r"(r[3]) : "r"(addr));
}
__device__ __forceinline__ void ldsm4t(uint32_t r[4], uint32_t addr) {
    asm volatile("ldmatrix.sync.aligned.m8n8.x4.trans.shared.b16 {%0,%1,%2,%3}, [%4];"
                 : "=r"(r[0]), "=r"(r[1]), "=r"(r[2]), "=r"(r[3]) : "r"(addr));
}
__device__ __forceinline__ void mma16816(float c[4], const uint32_t a[4],
                                         uint32_t b0, uint32_t b1) {
    asm volatile("mma.sync.aligned.m16n8k16.row.col.f32.bf16.bf16.f32 "
                 "{%0,%1,%2,%3}, {%4,%5,%6,%7}, {%8,%9}, {%0,%1,%2,%3};"
                 : "+f"(c[0]), "+f"(c[1]), "+f"(c[2]), "+f"(c[3])
                 : "r"(a[0]), "r"(a[1]), "r"(a[2]), "r"(a[3]), "r"(b0), "r"(b1));
}
__device__ __forceinline__ void cpa16(uint32_t dst, const void* src) {
    asm volatile("cp.async.cg.shared.global [%0], [%1], 16;" :: "r"(dst), "l"(src));
}

// ---------------------------------------------------------------------------
// split3: fp32 [rows,K] -> bf16 [rows,3K]. loblk 1: [hi|lo|hi]; 2: [hi|hi|lo]
// ---------------------------------------------------------------------------
__global__ void split3_kernel(const float* __restrict__ src,
                              __nv_bfloat16* __restrict__ dst,
                              int rows, int K, int loblk) {
    int t = blockIdx.x * blockDim.x + threadIdx.x;
    int per4 = K >> 2;
    if (t >= rows * per4) return;
    int r = t / per4, c4 = (t - r * per4) * 4;
    float4 v = ((const float4*)src)[t];

    __nv_bfloat16 h0 = __float2bfloat16(v.x), h1 = __float2bfloat16(v.y);
    __nv_bfloat16 h2 = __float2bfloat16(v.z), h3 = __float2bfloat16(v.w);
    uint2 hp = make_uint2(pk(h0, h1), pk(h2, h3));
    uint2 lp = make_uint2(pkf(v.x - __bfloat162float(h0), v.y - __bfloat162float(h1)),
                          pkf(v.z - __bfloat162float(h2), v.w - __bfloat162float(h3)));

    __nv_bfloat16* d0 = dst + (size_t)r * (3 * K) + c4;
    *(uint2*)(d0)         = hp;
    *(uint2*)(d0 + K)     = (loblk == 1) ? lp : hp;
    *(uint2*)(d0 + 2 * K) = (loblk == 1) ? hp : lp;
}

extern __shared__ char sh_raw[];

#define KSTRB 144   // bytes per smem row (72 bf16, odd multiple of 16B)

// ---------------------------------------------------------------------------
// gemm1: C = A[M,K]@B[N,K]^T with fused QKV split epilogue.
// 128x64 CTA tile, 128 threads (4 warps 2m x 2n), BK=64, 2-stage double
// buffer, 4 CTAs/SM. Fine tile granularity kills the wave-quantization tail.
// ---------------------------------------------------------------------------
#define G1_STG ((128 + 64) * KSTRB)      // 27648
#define G1_SMEM (2 * G1_STG)             // 55296

__global__ __launch_bounds__(128, 4)
void gemm_n64_qkv(const __nv_bfloat16* __restrict__ A,
                  const __nv_bfloat16* __restrict__ B,
                  __nv_bfloat16* __restrict__ Qd,
                  __nv_bfloat16* __restrict__ Kd,
                  __nv_bfloat16* __restrict__ Vd) {
    const int M_K = K3;   // 3072
    const uint32_t sb = smem_u32(sh_raw);
    const int tid = threadIdx.x, wid = tid >> 5, lane = tid & 31;
    const int bm = blockIdx.y * 128, bn = blockIdx.x * 64;
    const int wm = (wid >> 1) * 64, wn = (wid & 1) * 32;
    const int g = lane >> 2, tg = lane & 3;
    const int lrow = lane & 15, lcol = (lane >> 4) * 8;

    auto load_stage = [&](int s, int kk) {
        uint32_t abase = sb + (uint32_t)s * G1_STG;
        uint32_t bbase = abase + 128 * KSTRB;
#pragma unroll
        for (int i = 0; i < 12; ++i) {          // 1536 chunks over 128 threads
            int c = tid + i * 128;
            if (c < 1024) {
                int row = c >> 3, k16 = c & 7;
                cpa16(abase + row * KSTRB + k16 * 16,
                      A + (size_t)(bm + row) * M_K + kk + k16 * 8);
            } else {
                int row = (c - 1024) >> 3, k16 = c & 7;
                cpa16(bbase + row * KSTRB + k16 * 16,
                      B + (size_t)(bn + row) * M_K + kk + k16 * 8);
            }
        }
        asm volatile("cp.async.commit_group;" ::: "memory");
    };

    float acc[4][4][4];
#pragma unroll
    for (int i = 0; i < 4; ++i)
#pragma unroll
        for (int j = 0; j < 4; ++j)
#pragma unroll
            for (int e = 0; e < 4; ++e) acc[i][j][e] = 0.0f;

    const int NC = M_K / 64;   // 48
    load_stage(0, 0);

    for (int c = 0; c < NC; ++c) {
        asm volatile("cp.async.wait_group 0;" ::: "memory");
        __syncthreads();       // buffer c ready; buffer (c+1)&1 free (consumed c-1)
        if (c + 1 < NC) load_stage((c + 1) & 1, (c + 1) * 64);

        uint32_t abase = sb + (uint32_t)(c & 1) * G1_STG;
        uint32_t bbase = abase + 128 * KSTRB;
#pragma unroll
        for (int ks = 0; ks < 4; ++ks) {
            uint32_t a[4][4];
#pragma unroll
            for (int mt = 0; mt < 4; ++mt)
                ldsm4(a[mt], abase + (wm + mt * 16 + lrow) * KSTRB + (ks * 16 + lcol) * 2);
            uint32_t bf[4][2];
#pragma unroll
            for (int nb = 0; nb < 2; ++nb) {
                uint32_t r[4];
                ldsm4(r, bbase + (wn + nb * 16 + lrow) * KSTRB + (ks * 16 + lcol) * 2);
                bf[nb * 2][0] = r[0];     bf[nb * 2][1] = r[2];
                bf[nb * 2 + 1][0] = r[1]; bf[nb * 2 + 1][1] = r[3];
            }
#pragma unroll
            for (int mt = 0; mt < 4; ++mt)
#pragma unroll
                for (int nt = 0; nt < 4; ++nt)
                    mma16816(acc[mt][nt], a[mt], bf[nt][0], bf[nt][1]);
        }
    }

    // fused QKV split epilogue: [hi(64)|lo(64)] rows of 128 per (b,h)
#pragma unroll
    for (int nt = 0; nt < 4; ++nt) {
        int cbase = bn + wn + nt * 8 + tg * 2;
        int plane = cbase >> 10, rem = cbase & 1023;
        int h = rem >> 6, d = rem & 63;
        __nv_bfloat16* basep = (plane == 0) ? Qd : (plane == 1) ? Kd : Vd;
#pragma unroll
        for (int mt = 0; mt < 4; ++mt) {
#pragma unroll
            for (int rr = 0; rr < 2; ++rr) {
                int row = bm + wm + mt * 16 + g + rr * 8;
                int b = row >> 11, s = row & 2047;
                float v0 = acc[mt][nt][rr * 2], v1 = acc[mt][nt][rr * 2 + 1];
                __nv_bfloat16 h0 = __float2bfloat16(v0), h1 = __float2bfloat16(v1);
                uint32_t hi = pk(h0, h1);
                uint32_t lo = pkf(v0 - __bfloat162float(h0), v1 - __bfloat162float(h1));
                __nv_bfloat16* p = basep +
                    ((size_t)(b * 16 + h) * 2048 + s) * 128 + d;
                *(uint32_t*)(p)      = hi;
                *(uint32_t*)(p + 64) = lo;
            }
        }
    }
}

// ---------------------------------------------------------------------------
// gemm2: C = A[M,K] @ B[N,K]^T, fp32 out. 128x128 tile, 256 thr, 3-stage.
// (round-10 proven)
// ---------------------------------------------------------------------------
#define BM 128
#define BN 128
#define BK 64
#define STG_BYTES ((BM + BN) * KSTRB)   // 36864
#define GEMM_SMEM (3 * STG_BYTES)       // 110592

__global__ __launch_bounds__(256, 2)
void gemm_mma(const __nv_bfloat16* __restrict__ A,
              const __nv_bfloat16* __restrict__ B,
              float* __restrict__ C, int M, int N, int K) {
    const uint32_t sb = smem_u32(sh_raw);
    const int tid = threadIdx.x, wid = tid >> 5, lane = tid & 31;
    const int bm = blockIdx.y * BM, bn = blockIdx.x * BN;
    const int wm = (wid >> 2) * 64, wn = (wid & 3) * 32;
    const int g = lane >> 2, tg = lane & 3;
    const int lrow = lane & 15, lcol = (lane >> 4) * 8;

    auto load_stage = [&](int s, int kk) {
        uint32_t abase = sb + (uint32_t)s * STG_BYTES;
        uint32_t bbase = abase + BM * KSTRB;
#pragma unroll
        for (int i = 0; i < 8; ++i) {
            int c = tid + i * 256;
            if (c < 1024) {
                int row = c >> 3, k16 = c & 7;
                cpa16(abase + row * KSTRB + k16 * 16,
                      A + (size_t)(bm + row) * K + kk + k16 * 8);
            } else {
                int row = (c - 1024) >> 3, k16 = c & 7;
                cpa16(bbase + row * KSTRB + k16 * 16,
                      B + (size_t)(bn + row) * K + kk + k16 * 8);
            }
        }
        asm volatile("cp.async.commit_group;" ::: "memory");
    };

    float acc[4][4][4];
#pragma unroll
    for (int i = 0; i < 4; ++i)
#pragma unroll
        for (int j = 0; j < 4; ++j)
#pragma unroll
            for (int e = 0; e < 4; ++e) acc[i][j][e] = 0.0f;

    const int NC = K / BK;
    load_stage(0, 0);
    load_stage(1, BK);

    int st = 0;
    for (int c = 0; c < NC; ++c) {
        if (c + 1 < NC) asm volatile("cp.async.wait_group 1;" ::: "memory");
        else            asm volatile("cp.async.wait_group 0;" ::: "memory");
        __syncthreads();
        if (c + 2 < NC) {
            int ns = st + 2; if (ns >= 3) ns -= 3;
            load_stage(ns, (c + 2) * BK);
        }

        uint32_t abase = sb + (uint32_t)st * STG_BYTES;
        uint32_t bbase = abase + BM * KSTRB;
#pragma unroll
        for (int ks = 0; ks < 4; ++ks) {
            uint32_t a[4][4];
#pragma unroll
            for (int mt = 0; mt < 4; ++mt)
                ldsm4(a[mt], abase + (wm + mt * 16 + lrow) * KSTRB + (ks * 16 + lcol) * 2);
            uint32_t bf[4][2];
#pragma unroll
            for (int nb = 0; nb < 2; ++nb) {
                uint32_t r[4];
                ldsm4(r, bbase + (wn + nb * 16 + lrow) * KSTRB + (ks * 16 + lcol) * 2);
                bf[nb * 2][0] = r[0];     bf[nb * 2][1] = r[2];
                bf[nb * 2 + 1][0] = r[1]; bf[nb * 2 + 1][1] = r[3];
            }
#pragma unroll
            for (int mt = 0; mt < 4; ++mt)
#pragma unroll
                for (int nt = 0; nt < 4; ++nt)
                    mma16816(acc[mt][nt], a[mt], bf[nt][0], bf[nt][1]);
        }
        ++st; if (st >= 3) st = 0;
    }

#pragma unroll
    for (int mt = 0; mt < 4; ++mt) {
        int r0 = bm + wm + mt * 16 + g;
#pragma unroll
        for (int nt = 0; nt < 4; ++nt) {
            int col = bn + wn + nt * 8 + tg * 2;
            *(float2*)(C + (size_t)r0 * N + col) =
                make_float2(acc[mt][nt][0], acc[mt][nt][1]);
            *(float2*)(C + (size_t)(r0 + 8) * N + col) =
                make_float2(acc[mt][nt][2], acc[mt][nt][3]);
        }
    }
}

// ---------------------------------------------------------------------------
// Flash attention (round-10 proven): BR=128, BC=64, 256 thr, paired q-tiles,
// double-buffered K/V, fragment-reuse 3-term QK, exp2 softmax. E' [hi|lo|hi].
// ---------------------------------------------------------------------------
#define STR 136
#define Q_EL  (128 * STR)
#define KV_EL (64 * STR)
#define ATT_SMEM ((Q_EL + 4 * KV_EL) * 2)   // 104448

__global__ __launch_bounds__(256, 2)
void attn_mma5(const __nv_bfloat16* __restrict__ Qg,
               const __nv_bfloat16* __restrict__ Kg,
               const __nv_bfloat16* __restrict__ Vg,
               __nv_bfloat16* __restrict__ Eo) {
    const uint32_t sbQ = smem_u32(sh_raw);

    const int tid = threadIdx.x, wid = tid >> 5, lane = tid & 31;
    const int h = blockIdx.y, b = blockIdx.z;
    const size_t bh = (size_t)(b * 16 + h);
    const int g = lane >> 2, tg = lane & 3;
    const int lrow = lane & 15, lcol = (lane >> 4) * 8;
    const float scale = 0.125f * 1.44269504089f;

    auto load_kv = [&](int buf, int k0) {
        uint32_t kb = sbQ + (Q_EL + buf * 2 * KV_EL) * 2;
        uint32_t vb = kb + KV_EL * 2;
        const __nv_bfloat16* kg = Kg + (bh * 2048 + k0) * 128;
        const __nv_bfloat16* vg = Vg + (bh * 2048 + k0) * 128;
#pragma unroll
        for (int i = 0; i < 4; ++i) {
            int c = tid + i * 256;
            int row = c >> 4, cg = c & 15;
            cpa16(kb + (row * STR + cg * 8) * 2, kg + row * 128 + cg * 8);
            cpa16(vb + (row * STR + cg * 8) * 2, vg + row * 128 + cg * 8);
        }
        asm volatile("cp.async.commit_group;" ::: "memory");
    };

#pragma unroll 1
    for (int ph = 0; ph < 2; ++ph) {
        const int qi = ph ? (int)blockIdx.x : 15 - (int)blockIdx.x;
        const int q0 = qi * 128;
        const int ntiles = 2 * qi + 2;
        const int rowg0 = q0 + wid * 16 + g, rowg1 = rowg0 + 8;

        {
            const __nv_bfloat16* qg = Qg + (bh * 2048 + q0) * 128;
#pragma unroll
            for (int i = 0; i < 8; ++i) {
                int c = tid + i * 256;
                int row = c >> 4, cg = c & 15;
                cpa16(sbQ + (row * STR + cg * 8) * 2, qg + row * 128 + cg * 8);
            }
            asm volatile("cp.async.commit_group;" ::: "memory");
        }
        load_kv(0, 0);

        float m0 = -1e30f, m1 = -1e30f, l0 = 0.0f, l1 = 0.0f;
        float o[8][4];
#pragma unroll
        for (int i = 0; i < 8; ++i)
#pragma unroll
            for (int j = 0; j < 4; ++j) o[i][j] = 0.0f;

        for (int t = 0; t < ntiles; ++t) {
            const int k0 = t * 64;
            asm volatile("cp.async.wait_group 0;" ::: "memory");
            __syncthreads();
            if (t + 1 < ntiles) load_kv((t + 1) & 1, (t + 1) * 64);

            const uint32_t kbase = sbQ + (Q_EL + (t & 1) * 2 * KV_EL) * 2;
            const uint32_t vbase = kbase + KV_EL * 2;

            float s[8][4];
#pragma unroll
            for (int i = 0; i < 8; ++i)
#pragma unroll
                for (int j = 0; j < 4; ++j) s[i][j] = 0.0f;

#pragma unroll
            for (int i = 0; i < 4; ++i) {
                uint32_t qa0[4], qa1[4];
                ldsm4(qa0, sbQ + ((wid * 16 + lrow) * STR + i * 16 + lcol) * 2);
                ldsm4(qa1, sbQ + ((wid * 16 + lrow) * STR + (i + 4) * 16 + lcol) * 2);
#pragma unroll
                for (int nb = 0; nb < 4; ++nb) {
                    uint32_t r0[4], r1[4];
                    ldsm4(r0, kbase + ((nb * 16 + lrow) * STR + i * 16 + lcol) * 2);
                    ldsm4(r1, kbase + ((nb * 16 + lrow) * STR + (i + 4) * 16 + lcol) * 2);
                    mma16816(s[nb * 2],     qa0, r0[0], r0[2]);
                    mma16816(s[nb * 2 + 1], qa0, r0[1], r0[3]);
                    mma16816(s[nb * 2],     qa1, r0[0], r0[2]);
                    mma16816(s[nb * 2 + 1], qa1, r0[1], r0[3]);
                    mma16816(s[nb * 2],     qa0, r1[0], r1[2]);
                    mma16816(s[nb * 2 + 1], qa0, r1[1], r1[3]);
                }
            }

            if (t >= ntiles - 2) {
#pragma unroll
                for (int nt = 0; nt < 8; ++nt)
#pragma unroll
                    for (int ee = 0; ee < 4; ++ee) {
                        int col = k0 + nt * 8 + tg * 2 + (ee & 1);
                        int row = (ee < 2) ? rowg0 : rowg1;
                        if (col > row) s[nt][ee] = -1e30f;
                        else           s[nt][ee] *= scale;
                    }
            } else {
#pragma unroll
                for (int nt = 0; nt < 8; ++nt)
#pragma unroll
                    for (int ee = 0; ee < 4; ++ee) s[nt][ee] *= scale;
            }

            float rmax0 = -1e30f, rmax1 = -1e30f;
#pragma unroll
            for (int nt = 0; nt < 8; ++nt) {
                rmax0 = fmaxf(rmax0, fmaxf(s[nt][0], s[nt][1]));
                rmax1 = fmaxf(rmax1, fmaxf(s[nt][2], s[nt][3]));
            }
            rmax0 = fmaxf(rmax0, __shfl_xor_sync(0xffffffffu, rmax0, 1));
            rmax0 = fmaxf(rmax0, __shfl_xor_sync(0xffffffffu, rmax0, 2));
            rmax1 = fmaxf(rmax1, __shfl_xor_sync(0xffffffffu, rmax1, 1));
            rmax1 = fmaxf(rmax1, __shfl_xor_sync(0xffffffffu, rmax1, 2));

            float mn0 = fmaxf(m0, rmax0), mn1 = fmaxf(m1, rmax1);
            float al0 = exp2f(m0 - mn0), al1 = exp2f(m1 - mn1);
            m0 = mn0; m1 = mn1;

            float rs0 = 0.0f, rs1 = 0.0f;
#pragma unroll
            for (int nt = 0; nt < 8; ++nt) {
                s[nt][0] = exp2f(s[nt][0] - m0);
                s[nt][1] = exp2f(s[nt][1] - m0);
                s[nt][2] = exp2f(s[nt][2] - m1);
                s[nt][3] = exp2f(s[nt][3] - m1);
                rs0 += s[nt][0] + s[nt][1];
                rs1 += s[nt][2] + s[nt][3];
            }
            rs0 += __shfl_xor_sync(0xffffffffu, rs0, 1);
            rs0 += __shfl_xor_sync(0xffffffffu, rs0, 2);
            rs1 += __shfl_xor_sync(0xffffffffu, rs1, 1);
            rs1 += __shfl_xor_sync(0xffffffffu, rs1, 2);
            l0 = l0 * al0 + rs0;
            l1 = l1 * al1 + rs1;
#pragma unroll
            for (int nt = 0; nt < 8; ++nt) {
                o[nt][0] *= al0; o[nt][1] *= al0;
                o[nt][2] *= al1; o[nt][3] *= al1;
            }

            uint32_t pfh[4][4], pfl[4][4];
#pragma unroll
            for (int kc = 0; kc < 4; ++kc) {
                const float* se = s[kc * 2];
                const float* so = s[kc * 2 + 1];
                __nv_bfloat16 he0 = __float2bfloat16(se[0]), he1 = __float2bfloat16(se[1]);
                __nv_bfloat16 he2 = __float2bfloat16(se[2]), he3 = __float2bfloat16(se[3]);
                __nv_bfloat16 ho0 = __float2bfloat16(so[0]), ho1 = __float2bfloat16(so[1]);
                __nv_bfloat16 ho2 = __float2bfloat16(so[2]), ho3 = __float2bfloat16(so[3]);
                pfh[kc][0] = pk(he0, he1); pfh[kc][1] = pk(he2, he3);
                pfh[kc][2] = pk(ho0, ho1); pfh[kc][3] = pk(ho2, ho3);
                pfl[kc][0] = pkf(se[0] - __bfloat162float(he0), se[1] - __bfloat162float(he1));
                pfl[kc][1] = pkf(se[2] - __bfloat162float(he2), se[3] - __bfloat162float(he3));
                pfl[kc][2] = pkf(so[0] - __bfloat162float(ho0), so[1] - __bfloat162float(ho1));
                pfl[kc][3] = pkf(so[2] - __bfloat162float(ho2), so[3] - __bfloat162float(ho3));
            }

#pragma unroll
            for (int kc = 0; kc < 4; ++kc) {
#pragma unroll
                for (int db = 0; db < 4; ++db) {
                    uint32_t rh[4];
                    ldsm4t(rh, vbase + ((kc * 16 + lrow) * STR + db * 16 + lcol) * 2);
                    mma16816(o[db * 2],     pfh[kc], rh[0], rh[1]);
                    mma16816(o[db * 2 + 1], pfh[kc], rh[2], rh[3]);
                    mma16816(o[db * 2],     pfl[kc], rh[0], rh[1]);
                    mma16816(o[db * 2 + 1], pfl[kc], rh[2], rh[3]);
                    uint32_t rl[4];
                    ldsm4t(rl, vbase + ((kc * 16 + lrow) * STR + 64 + db * 16 + lcol) * 2);
                    mma16816(o[db * 2],     pfh[kc], rl[0], rl[1]);
                    mma16816(o[db * 2 + 1], pfh[kc], rl[2], rl[3]);
                }
            }
        }

        float inv0 = 1.0f / l0, inv1 = 1.0f / l1;
        size_t r0 = (size_t)(b * 2048) + rowg0;
        size_t r1 = (size_t)(b * 2048) + rowg1;
#pragma unroll
        for (int nt = 0; nt < 8; ++nt) {
            int col = h * 64 + nt * 8 + tg * 2;
            float a0 = o[nt][0] * inv0, a1 = o[nt][1] * inv0;
            float b0 = o[nt][2] * inv1, b1 = o[nt][3] * inv1;
            __nv_bfloat16 ah0 = __float2bfloat16(a0), ah1 = __float2bfloat16(a1);
            __nv_bfloat16 bh0 = __float2bfloat16(b0), bh1 = __float2bfloat16(b1);
            uint32_t ahi = pk(ah0, ah1);
            uint32_t alo = pkf(a0 - __bfloat162float(ah0), a1 - __bfloat162float(ah1));
            uint32_t bhi = pk(bh0, bh1);
            uint32_t blo = pkf(b0 - __bfloat162float(bh0), b1 - __bfloat162float(bh1));
            __nv_bfloat16* p0 = Eo + r0 * K3 + col;
            __nv_bfloat16* p1 = Eo + r1 * K3 + col;
            *(uint32_t*)(p0)        = ahi;
            *(uint32_t*)(p0 + 1024) = alo;
            *(uint32_t*)(p0 + 2048) = ahi;
            *(uint32_t*)(p1)        = bhi;
            *(uint32_t*)(p1 + 1024) = blo;
            *(uint32_t*)(p1 + 2048) = bhi;
        }

        __syncthreads();
    }
}

// ---------------------------------------------------------------------------
// launch
// ---------------------------------------------------------------------------
extern "C" void kernel_launch(void* const* d_in, const int* in_sizes, int n_in,
                              void* d_out, int out_size) {
    (void)in_sizes; (void)n_in; (void)out_size;
    const float* x    = (const float*)d_in[0];
    const float* wqkv = (const float*)d_in[1];
    const float* w0   = (const float*)d_in[2];
    float* out = (float*)d_out;

    __nv_bfloat16 *a2, *w2, *qd, *kd, *vd;
    cudaGetSymbolAddress((void**)&a2, g_a2);
    cudaGetSymbolAddress((void**)&w2, g_w2);
    cudaGetSymbolAddress((void**)&qd, g_q);
    cudaGetSymbolAddress((void**)&kd, g_k);
    cudaGetSymbolAddress((void**)&vd, g_v);

    cudaFuncSetAttribute(gemm_n64_qkv,
                         cudaFuncAttributeMaxDynamicSharedMemorySize, G1_SMEM);
    cudaFuncSetAttribute(gemm_mma,
                         cudaFuncAttributeMaxDynamicSharedMemorySize, GEMM_SMEM);
    cudaFuncSetAttribute(attn_mma5,
                         cudaFuncAttributeMaxDynamicSharedMemorySize, ATT_SMEM);

    const int M = 4096;

    split3_kernel<<<(M * E_DIM / 4 + 255) / 256, 256>>>(x, a2, M, E_DIM, 1);
    split3_kernel<<<(3 * E_DIM * E_DIM / 4 + 255) / 256, 256>>>(wqkv, w2, 3 * E_DIM, E_DIM, 2);

    // gemm1: QKV with fused split epilogue; fine 128x64 tiles (48 x 32 grid)
    gemm_n64_qkv<<<dim3(3 * E_DIM / 64, M / 128), 128, G1_SMEM>>>(a2, w2, qd, kd, vd);

    // attention -> E' (into g_a2); paired q-tiles: grid.x = 8
    attn_mma5<<<dim3(8, 16, 2), 256, ATT_SMEM>>>(qd, kd, vd, a2);

    split3_kernel<<<(E_DIM * E_DIM / 4 + 255) / 256, 256>>>(w0, w2, E_DIM, E_DIM, 2);

    // gemm2: out projection (128x128 tiles, fp32 epilogue)
    gemm_mma<<<dim3(E_DIM / BN, M / BM), 256, GEMM_SMEM>>>(
        a2, w2, out, M, E_DIM, K3);
}

// round 14
// speedup vs baseline: 2.5121x; 1.4495x over previous
#include <cuda_runtime.h>
#include <cuda_fp16.h>
#include <cstdint>
#include <cstddef>

// ---------------------------------------------------------------------------
// MHA: B=2, S=2048, E=1024, H=16, D=64, fp32, causal.
// fp16 2-term split everywhere (left operand hi+lo, right operand hi only):
//  split2(x)->[Xh|Xl], split2(wqkv)->[Wh|Wh]   (K'=2048)
//  gemm1 (128x64 tiles, fused epi): Q [qh|ql](128), K [kh](64), V [vh](64)
//  attn: BR=128 paired q-tiles, double-buffered K/V, 2-term QK/PV
//        -> E' [Eh|El] (2048)
//  split2(w0)->[Wh|Wh] ; gemm2 (128x128) -> fp32 out
// Per-matmul RMS error ~2^-12/sqrt(3) ~ 1.4e-4; chain ~3e-4 < 1e-3.
// ---------------------------------------------------------------------------

#define S_LEN   2048
#define E_DIM   1024
#define K2      2048

__device__ __half g_a2[4096 * K2];            // X' then E'  [hi|lo]
__device__ __half g_w2[3072 * K2];            // Wqkv' then W0'  [hi|hi]
__device__ __half g_q [32 * 2048 * 128];      // Q [qh|ql] per (b,h)
__device__ __half g_k [32 * 2048 * 64];       // K hi only
__device__ __half g_v [32 * 2048 * 64];       // V hi only

// ---------------------------------------------------------------------------
__device__ __forceinline__ uint32_t smem_u32(const void* p) {
    uint32_t a;
    asm("{ .reg .u64 t; cvta.to.shared.u64 t, %1; cvt.u32.u64 %0, t; }"
        : "=r"(a) : "l"(p));
    return a;
}
__device__ __forceinline__ uint32_t pkh(__half a, __half b) {
    __half2 t = __halves2half2(a, b);
    return *reinterpret_cast<uint32_t*>(&t);
}
__device__ __forceinline__ uint32_t pkhf(float a, float b) {
    return pkh(__float2half_rn(a), __float2half_rn(b));
}
__device__ __forceinline__ void ldsm4(uint32_t r[4], uint32_t addr) {
    asm volatile("ldmatrix.sync.aligned.m8n8.x4.shared.b16 {%0,%1,%2,%3}, [%4];"
                 : "=r"(r[0]), "=r"(r[1]), "=r"(r[2]), "=r"(r[3]) : "r"(addr));
}
__device__ __forceinline__ void ldsm4t(uint32_t r[4], uint32_t addr) {
    asm volatile("ldmatrix.sync.aligned.m8n8.x4.trans.shared.b16 {%0,%1,%2,%3}, [%4];"
                 : "=r"(r[0]), "=r"(r[1]), "=r"(r[2]), "=r"(r[3]) : "r"(addr));
}
__device__ __forceinline__ void mma16816(float c[4], const uint32_t a[4],
                                         uint32_t b0, uint32_t b1) {
    asm volatile("mma.sync.aligned.m16n8k16.row.col.f32.f16.f16.f32 "
                 "{%0,%1,%2,%3}, {%4,%5,%6,%7}, {%8,%9}, {%0,%1,%2,%3};"
                 : "+f"(c[0]), "+f"(c[1]), "+f"(c[2]), "+f"(c[3])
                 : "r"(a[0]), "r"(a[1]), "r"(a[2]), "r"(a[3]), "r"(b0), "r"(b1));
}
__device__ __forceinline__ void cpa16(uint32_t dst, const void* src) {
    asm volatile("cp.async.cg.shared.global [%0], [%1], 16;" :: "r"(dst), "l"(src));
}

// ---------------------------------------------------------------------------
// split2: fp32 [rows,K] -> fp16 [rows,2K].
//   dup==0 (A-side): [hi | lo],  dup==1 (B-side): [hi | hi]
// ---------------------------------------------------------------------------
__global__ void split2_kernel(const float* __restrict__ src,
                              __half* __restrict__ dst,
                              int rows, int K, int dup) {
    int t = blockIdx.x * blockDim.x + threadIdx.x;
    int per4 = K >> 2;
    if (t >= rows * per4) return;
    int r = t / per4, c4 = (t - r * per4) * 4;
    float4 v = ((const float4*)src)[t];

    __half h0 = __float2half_rn(v.x), h1 = __float2half_rn(v.y);
    __half h2 = __float2half_rn(v.z), h3 = __float2half_rn(v.w);
    uint2 hp = make_uint2(pkh(h0, h1), pkh(h2, h3));
    uint2 lp = make_uint2(pkhf(v.x - __half2float(h0), v.y - __half2float(h1)),
                          pkhf(v.z - __half2float(h2), v.w - __half2float(h3)));

    __half* d0 = dst + (size_t)r * (2 * K) + c4;
    *(uint2*)(d0)     = hp;
    *(uint2*)(d0 + K) = dup ? hp : lp;
}

extern __shared__ char sh_raw[];

#define KSTRB 144   // bytes per smem row (72 fp16, odd multiple of 16B)

// ---------------------------------------------------------------------------
// gemm1: C = A[M,2048]@B[N,2048]^T, fused QKV epilogue ->
//   Q [qh|ql] (128 cols), K [kh] (64), V [vh] (64).
// 128x64 CTA tile, 128 threads, BK=64, 2-stage, 4 CTAs/SM.
// ---------------------------------------------------------------------------
#define G1_STG ((128 + 64) * KSTRB)      // 27648
#define G1_SMEM (2 * G1_STG)             // 55296

__global__ __launch_bounds__(128, 4)
void gemm_n64_qkv(const __half* __restrict__ A,
                  const __half* __restrict__ B,
                  __half* __restrict__ Qd,
                  __half* __restrict__ Kd,
                  __half* __restrict__ Vd) {
    const uint32_t sb = smem_u32(sh_raw);
    const int tid = threadIdx.x, wid = tid >> 5, lane = tid & 31;
    const int bm = blockIdx.y * 128, bn = blockIdx.x * 64;
    const int wm = (wid >> 1) * 64, wn = (wid & 1) * 32;
    const int g = lane >> 2, tg = lane & 3;
    const int lrow = lane & 15, lcol = (lane >> 4) * 8;

    auto load_stage = [&](int s, int kk) {
        uint32_t abase = sb + (uint32_t)s * G1_STG;
        uint32_t bbase = abase + 128 * KSTRB;
#pragma unroll
        for (int i = 0; i < 12; ++i) {          // 1536 chunks over 128 threads
            int c = tid + i * 128;
            if (c < 1024) {
                int row = c >> 3, k16 = c & 7;
                cpa16(abase + row * KSTRB + k16 * 16,
                      A + (size_t)(bm + row) * K2 + kk + k16 * 8);
            } else {
                int row = (c - 1024) >> 3, k16 = c & 7;
                cpa16(bbase + row * KSTRB + k16 * 16,
                      B + (size_t)(bn + row) * K2 + kk + k16 * 8);
            }
        }
        asm volatile("cp.async.commit_group;" ::: "memory");
    };

    float acc[4][4][4];
#pragma unroll
    for (int i = 0; i < 4; ++i)
#pragma unroll
        for (int j = 0; j < 4; ++j)
#pragma unroll
            for (int e = 0; e < 4; ++e) acc[i][j][e] = 0.0f;

    const int NC = K2 / 64;   // 32
    load_stage(0, 0);

    for (int c = 0; c < NC; ++c) {
        asm volatile("cp.async.wait_group 0;" ::: "memory");
        __syncthreads();
        if (c + 1 < NC) load_stage((c + 1) & 1, (c + 1) * 64);

        uint32_t abase = sb + (uint32_t)(c & 1) * G1_STG;
        uint32_t bbase = abase + 128 * KSTRB;
#pragma unroll
        for (int ks = 0; ks < 4; ++ks) {
            uint32_t a[4][4];
#pragma unroll
            for (int mt = 0; mt < 4; ++mt)
                ldsm4(a[mt], abase + (wm + mt * 16 + lrow) * KSTRB + (ks * 16 + lcol) * 2);
            uint32_t bf[4][2];
#pragma unroll
            for (int nb = 0; nb < 2; ++nb) {
                uint32_t r[4];
                ldsm4(r, bbase + (wn + nb * 16 + lrow) * KSTRB + (ks * 16 + lcol) * 2);
                bf[nb * 2][0] = r[0];     bf[nb * 2][1] = r[2];
                bf[nb * 2 + 1][0] = r[1]; bf[nb * 2 + 1][1] = r[3];
            }
#pragma unroll
            for (int mt = 0; mt < 4; ++mt)
#pragma unroll
                for (int nt = 0; nt < 4; ++nt)
                    mma16816(acc[mt][nt], a[mt], bf[nt][0], bf[nt][1]);
        }
    }

    // fused QKV epilogue: Q split hi/lo; K,V hi only
#pragma unroll
    for (int nt = 0; nt < 4; ++nt) {
        int cbase = bn + wn + nt * 8 + tg * 2;
        int plane = cbase >> 10, rem = cbase & 1023;
        int h = rem >> 6, d = rem & 63;
#pragma unroll
        for (int mt = 0; mt < 4; ++mt) {
#pragma unroll
            for (int rr = 0; rr < 2; ++rr) {
                int row = bm + wm + mt * 16 + g + rr * 8;
                int b = row >> 11, s = row & 2047;
                size_t bhs = (size_t)(b * 16 + h) * 2048 + s;
                float v0 = acc[mt][nt][rr * 2], v1 = acc[mt][nt][rr * 2 + 1];
                __half h0 = __float2half_rn(v0), h1 = __float2half_rn(v1);
                uint32_t hi = pkh(h0, h1);
                if (plane == 0) {
                    uint32_t lo = pkhf(v0 - __half2float(h0), v1 - __half2float(h1));
                    __half* p = Qd + bhs * 128 + d;
                    *(uint32_t*)(p)      = hi;
                    *(uint32_t*)(p + 64) = lo;
                } else if (plane == 1) {
                    *(uint32_t*)(Kd + bhs * 64 + d) = hi;
                } else {
                    *(uint32_t*)(Vd + bhs * 64 + d) = hi;
                }
            }
        }
    }
}

// ---------------------------------------------------------------------------
// gemm2: C = A[M,2048] @ B[N,2048]^T, fp32 out. 128x128 tile, 3-stage.
// ---------------------------------------------------------------------------
#define BM 128
#define BN 128
#define BK 64
#define STG_BYTES ((BM + BN) * KSTRB)   // 36864
#define GEMM_SMEM (3 * STG_BYTES)       // 110592

__global__ __launch_bounds__(256, 2)
void gemm_mma(const __half* __restrict__ A,
              const __half* __restrict__ B,
              float* __restrict__ C, int M, int N, int K) {
    const uint32_t sb = smem_u32(sh_raw);
    const int tid = threadIdx.x, wid = tid >> 5, lane = tid & 31;
    const int bm = blockIdx.y * BM, bn = blockIdx.x * BN;
    const int wm = (wid >> 2) * 64, wn = (wid & 3) * 32;
    const int g = lane >> 2, tg = lane & 3;
    const int lrow = lane & 15, lcol = (lane >> 4) * 8;

    auto load_stage = [&](int s, int kk) {
        uint32_t abase = sb + (uint32_t)s * STG_BYTES;
        uint32_t bbase = abase + BM * KSTRB;
#pragma unroll
        for (int i = 0; i < 8; ++i) {
            int c = tid + i * 256;
            if (c < 1024) {
                int row = c >> 3, k16 = c & 7;
                cpa16(abase + row * KSTRB + k16 * 16,
                      A + (size_t)(bm + row) * K + kk + k16 * 8);
            } else {
                int row = (c - 1024) >> 3, k16 = c & 7;
                cpa16(bbase + row * KSTRB + k16 * 16,
                      B + (size_t)(bn + row) * K + kk + k16 * 8);
            }
        }
        asm volatile("cp.async.commit_group;" ::: "memory");
    };

    float acc[4][4][4];
#pragma unroll
    for (int i = 0; i < 4; ++i)
#pragma unroll
        for (int j = 0; j < 4; ++j)
#pragma unroll
            for (int e = 0; e < 4; ++e) acc[i][j][e] = 0.0f;

    const int NC = K / BK;
    load_stage(0, 0);
    load_stage(1, BK);

    int st = 0;
    for (int c = 0; c < NC; ++c) {
        if (c + 1 < NC) asm volatile("cp.async.wait_group 1;" ::: "memory");
        else            asm volatile("cp.async.wait_group 0;" ::: "memory");
        __syncthreads();
        if (c + 2 < NC) {
            int ns = st + 2; if (ns >= 3) ns -= 3;
            load_stage(ns, (c + 2) * BK);
        }

        uint32_t abase = sb + (uint32_t)st * STG_BYTES;
        uint32_t bbase = abase + BM * KSTRB;
#pragma unroll
        for (int ks = 0; ks < 4; ++ks) {
            uint32_t a[4][4];
#pragma unroll
            for (int mt = 0; mt < 4; ++mt)
                ldsm4(a[mt], abase + (wm + mt * 16 + lrow) * KSTRB + (ks * 16 + lcol) * 2);
            uint32_t bf[4][2];
#pragma unroll
            for (int nb = 0; nb < 2; ++nb) {
                uint32_t r[4];
                ldsm4(r, bbase + (wn + nb * 16 + lrow) * KSTRB + (ks * 16 + lcol) * 2);
                bf[nb * 2][0] = r[0];     bf[nb * 2][1] = r[2];
                bf[nb * 2 + 1][0] = r[1]; bf[nb * 2 + 1][1] = r[3];
            }
#pragma unroll
            for (int mt = 0; mt < 4; ++mt)
#pragma unroll
                for (int nt = 0; nt < 4; ++nt)
                    mma16816(acc[mt][nt], a[mt], bf[nt][0], bf[nt][1]);
        }
        ++st; if (st >= 3) st = 0;
    }

#pragma unroll
    for (int mt = 0; mt < 4; ++mt) {
        int r0 = bm + wm + mt * 16 + g;
#pragma unroll
        for (int nt = 0; nt < 4; ++nt) {
            int col = bn + wn + nt * 8 + tg * 2;
            *(float2*)(C + (size_t)r0 * N + col) =
                make_float2(acc[mt][nt][0], acc[mt][nt][1]);
            *(float2*)(C + (size_t)(r0 + 8) * N + col) =
                make_float2(acc[mt][nt][2], acc[mt][nt][3]);
        }
    }
}

// ---------------------------------------------------------------------------
// Flash attention fp16-2-term: BR=128, BC=64, 256 thr, paired q-tiles,
// double-buffered K/V. Q [qh|ql] (128 cols); K,V hi-only (64 cols).
// QK = (Qh+Ql)Kh ; PV = (Ph+Pl)Vh. exp2 softmax. E' -> [Eh|El] (2048).
// ---------------------------------------------------------------------------
#define QSTR 136                 // Q smem stride (elements)
#define KSTR 72                  // K/V smem stride
#define Q_EL  (128 * QSTR)       // 17408
#define KV_EL (64 * KSTR)        // 4608
#define ATT_SMEM ((Q_EL + 4 * KV_EL) * 2)   // 71680

__global__ __launch_bounds__(256, 2)
void attn_f16(const __half* __restrict__ Qg,
              const __half* __restrict__ Kg,
              const __half* __restrict__ Vg,
              __half* __restrict__ Eo) {
    const uint32_t sbQ = smem_u32(sh_raw);

    const int tid = threadIdx.x, wid = tid >> 5, lane = tid & 31;
    const int h = blockIdx.y, b = blockIdx.z;
    const size_t bh = (size_t)(b * 16 + h);
    const int g = lane >> 2, tg = lane & 3;
    const int lrow = lane & 15, lcol = (lane >> 4) * 8;
    const float scale = 0.125f * 1.44269504089f;

    auto load_kv = [&](int buf, int k0) {
        uint32_t kb = sbQ + (Q_EL + buf * 2 * KV_EL) * 2;
        uint32_t vb = kb + KV_EL * 2;
        const __half* kg = Kg + (bh * 2048 + k0) * 64;
        const __half* vg = Vg + (bh * 2048 + k0) * 64;
#pragma unroll
        for (int i = 0; i < 2; ++i) {
            int c = tid + i * 256;           // 512 chunks: 64 rows x 8
            int row = c >> 3, cg = c & 7;
            cpa16(kb + (row * KSTR + cg * 8) * 2, kg + row * 64 + cg * 8);
            cpa16(vb + (row * KSTR + cg * 8) * 2, vg + row * 64 + cg * 8);
        }
        asm volatile("cp.async.commit_group;" ::: "memory");
    };

#pragma unroll 1
    for (int ph = 0; ph < 2; ++ph) {
        const int qi = ph ? (int)blockIdx.x : 15 - (int)blockIdx.x;
        const int q0 = qi * 128;
        const int ntiles = 2 * qi + 2;
        const int rowg0 = q0 + wid * 16 + g, rowg1 = rowg0 + 8;

        {
            const __half* qg = Qg + (bh * 2048 + q0) * 128;
#pragma unroll
            for (int i = 0; i < 8; ++i) {
                int c = tid + i * 256;       // 2048 chunks: 128 rows x 16
                int row = c >> 4, cg = c & 15;
                cpa16(sbQ + (row * QSTR + cg * 8) * 2, qg + row * 128 + cg * 8);
            }
            asm volatile("cp.async.commit_group;" ::: "memory");
        }
        load_kv(0, 0);

        float m0 = -1e30f, m1 = -1e30f, l0 = 0.0f, l1 = 0.0f;
        float o[8][4];
#pragma unroll
        for (int i = 0; i < 8; ++i)
#pragma unroll
            for (int j = 0; j < 4; ++j) o[i][j] = 0.0f;

        for (int t = 0; t < ntiles; ++t) {
            const int k0 = t * 64;
            asm volatile("cp.async.wait_group 0;" ::: "memory");
            __syncthreads();
            if (t + 1 < ntiles) load_kv((t + 1) & 1, (t + 1) * 64);

            const uint32_t kbase = sbQ + (Q_EL + (t & 1) * 2 * KV_EL) * 2;
            const uint32_t vbase = kbase + KV_EL * 2;

            // ---- S = (Qh + Ql) * Kh^T
            float s[8][4];
#pragma unroll
            for (int i = 0; i < 8; ++i)
#pragma unroll
                for (int j = 0; j < 4; ++j) s[i][j] = 0.0f;

#pragma unroll
            for (int i = 0; i < 4; ++i) {
                uint32_t qa0[4], qa1[4];
                ldsm4(qa0, sbQ + ((wid * 16 + lrow) * QSTR + i * 16 + lcol) * 2);
                ldsm4(qa1, sbQ + ((wid * 16 + lrow) * QSTR + 64 + i * 16 + lcol) * 2);
#pragma unroll
                for (int nb = 0; nb < 4; ++nb) {
                    uint32_t r0[4];
                    ldsm4(r0, kbase + ((nb * 16 + lrow) * KSTR + i * 16 + lcol) * 2);
                    mma16816(s[nb * 2],     qa0, r0[0], r0[2]);
                    mma16816(s[nb * 2 + 1], qa0, r0[1], r0[3]);
                    mma16816(s[nb * 2],     qa1, r0[0], r0[2]);
                    mma16816(s[nb * 2 + 1], qa1, r0[1], r0[3]);
                }
            }

            // ---- scale (exp2 domain); mask only on diagonal tiles
            if (t >= ntiles - 2) {
#pragma unroll
                for (int nt = 0; nt < 8; ++nt)
#pragma unroll
                    for (int ee = 0; ee < 4; ++ee) {
                        int col = k0 + nt * 8 + tg * 2 + (ee & 1);
                        int row = (ee < 2) ? rowg0 : rowg1;
                        if (col > row) s[nt][ee] = -1e30f;
                        else           s[nt][ee] *= scale;
                    }
            } else {
#pragma unroll
                for (int nt = 0; nt < 8; ++nt)
#pragma unroll
                    for (int ee = 0; ee < 4; ++ee) s[nt][ee] *= scale;
            }

            // ---- online softmax (quad reductions, exp2 domain)
            float rmax0 = -1e30f, rmax1 = -1e30f;
#pragma unroll
            for (int nt = 0; nt < 8; ++nt) {
                rmax0 = fmaxf(rmax0, fmaxf(s[nt][0], s[nt][1]));
                rmax1 = fmaxf(rmax1, fmaxf(s[nt][2], s[nt][3]));
            }
            rmax0 = fmaxf(rmax0, __shfl_xor_sync(0xffffffffu, rmax0, 1));
            rmax0 = fmaxf(rmax0, __shfl_xor_sync(0xffffffffu, rmax0, 2));
            rmax1 = fmaxf(rmax1, __shfl_xor_sync(0xffffffffu, rmax1, 1));
            rmax1 = fmaxf(rmax1, __shfl_xor_sync(0xffffffffu, rmax1, 2));

            float mn0 = fmaxf(m0, rmax0), mn1 = fmaxf(m1, rmax1);
            float al0 = exp2f(m0 - mn0), al1 = exp2f(m1 - mn1);
            m0 = mn0; m1 = mn1;

            float rs0 = 0.0f, rs1 = 0.0f;
#pragma unroll
            for (int nt = 0; nt < 8; ++nt) {
                s[nt][0] = exp2f(s[nt][0] - m0);
                s[nt][1] = exp2f(s[nt][1] - m0);
                s[nt][2] = exp2f(s[nt][2] - m1);
                s[nt][3] = exp2f(s[nt][3] - m1);
                rs0 += s[nt][0] + s[nt][1];
                rs1 += s[nt][2] + s[nt][3];
            }
            rs0 += __shfl_xor_sync(0xffffffffu, rs0, 1);
            rs0 += __shfl_xor_sync(0xffffffffu, rs0, 2);
            rs1 += __shfl_xor_sync(0xffffffffu, rs1, 1);
            rs1 += __shfl_xor_sync(0xffffffffu, rs1, 2);
            l0 = l0 * al0 + rs0;
            l1 = l1 * al1 + rs1;
#pragma unroll
            for (int nt = 0; nt < 8; ++nt) {
                o[nt][0] *= al0; o[nt][1] *= al0;
                o[nt][2] *= al1; o[nt][3] *= al1;
            }

            // ---- P -> fp16 hi/lo A-fragments
            uint32_t pfh[4][4], pfl[4][4];
#pragma unroll
            for (int kc = 0; kc < 4; ++kc) {
                const float* se = s[kc * 2];
                const float* so = s[kc * 2 + 1];
                __half he0 = __float2half_rn(se[0]), he1 = __float2half_rn(se[1]);
                __half he2 = __float2half_rn(se[2]), he3 = __float2half_rn(se[3]);
                __half ho0 = __float2half_rn(so[0]), ho1 = __float2half_rn(so[1]);
                __half ho2 = __float2half_rn(so[2]), ho3 = __float2half_rn(so[3]);
                pfh[kc][0] = pkh(he0, he1); pfh[kc][1] = pkh(he2, he3);
                pfh[kc][2] = pkh(ho0, ho1); pfh[kc][3] = pkh(ho2, ho3);
                pfl[kc][0] = pkhf(se[0] - __half2float(he0), se[1] - __half2float(he1));
                pfl[kc][1] = pkhf(se[2] - __half2float(he2), se[3] - __half2float(he3));
                pfl[kc][2] = pkhf(so[0] - __half2float(ho0), so[1] - __half2float(ho1));
                pfl[kc][3] = pkhf(so[2] - __half2float(ho2), so[3] - __half2float(ho3));
            }

            // ---- O += (Ph + Pl) * Vh   (V via ldmatrix.trans)
#pragma unroll
            for (int kc = 0; kc < 4; ++kc) {
#pragma unroll
                for (int db = 0; db < 4; ++db) {
                    uint32_t rh[4];
                    ldsm4t(rh, vbase + ((kc * 16 + lrow) * KSTR + db * 16 + lcol) * 2);
                    mma16816(o[db * 2],     pfh[kc], rh[0], rh[1]);
                    mma16816(o[db * 2 + 1], pfh[kc], rh[2], rh[3]);
                    mma16816(o[db * 2],     pfl[kc], rh[0], rh[1]);
                    mma16816(o[db * 2 + 1], pfl[kc], rh[2], rh[3]);
                }
            }
        }

        // ---- epilogue: write E' [Eh|El] to Eo [4096, 2048]
        float inv0 = 1.0f / l0, inv1 = 1.0f / l1;
        size_t r0 = (size_t)(b * 2048) + rowg0;
        size_t r1 = (size_t)(b * 2048) + rowg1;
#pragma unroll
        for (int nt = 0; nt < 8; ++nt) {
            int col = h * 64 + nt * 8 + tg * 2;
            float a0 = o[nt][0] * inv0, a1 = o[nt][1] * inv0;
            float b0 = o[nt][2] * inv1, b1 = o[nt][3] * inv1;
            __half ah0 = __float2half_rn(a0), ah1 = __float2half_rn(a1);
            __half bh0 = __float2half_rn(b0), bh1 = __float2half_rn(b1);
            uint32_t ahi = pkh(ah0, ah1);
            uint32_t alo = pkhf(a0 - __half2float(ah0), a1 - __half2float(ah1));
            uint32_t bhi = pkh(bh0, bh1);
            uint32_t blo = pkhf(b0 - __half2float(bh0), b1 - __half2float(bh1));
            __half* p0 = Eo + r0 * K2 + col;
            __half* p1 = Eo + r1 * K2 + col;
            *(uint32_t*)(p0)        = ahi;
            *(uint32_t*)(p0 + 1024) = alo;
            *(uint32_t*)(p1)        = bhi;
            *(uint32_t*)(p1 + 1024) = blo;
        }

        __syncthreads();   // protect Q/K/V smem before next phase
    }
}

// ---------------------------------------------------------------------------
// launch
// ---------------------------------------------------------------------------
extern "C" void kernel_launch(void* const* d_in, const int* in_sizes, int n_in,
                              void* d_out, int out_size) {
    (void)in_sizes; (void)n_in; (void)out_size;
    const float* x    = (const float*)d_in[0];
    const float* wqkv = (const float*)d_in[1];
    const float* w0   = (const float*)d_in[2];
    float* out = (float*)d_out;

    __half *a2, *w2, *qd, *kd, *vd;
    cudaGetSymbolAddress((void**)&a2, g_a2);
    cudaGetSymbolAddress((void**)&w2, g_w2);
    cudaGetSymbolAddress((void**)&qd, g_q);
    cudaGetSymbolAddress((void**)&kd, g_k);
    cudaGetSymbolAddress((void**)&vd, g_v);

    cudaFuncSetAttribute(gemm_n64_qkv,
                         cudaFuncAttributeMaxDynamicSharedMemorySize, G1_SMEM);
    cudaFuncSetAttribute(gemm_mma,
                         cudaFuncAttributeMaxDynamicSharedMemorySize, GEMM_SMEM);
    cudaFuncSetAttribute(attn_f16,
                         cudaFuncAttributeMaxDynamicSharedMemorySize, ATT_SMEM);

    const int M = 4096;

    // 1) fp16 2-term splits of X and Wqkv
    split2_kernel<<<(M * E_DIM / 4 + 255) / 256, 256>>>(x, a2, M, E_DIM, 0);
    split2_kernel<<<(3 * E_DIM * E_DIM / 4 + 255) / 256, 256>>>(wqkv, w2, 3 * E_DIM, E_DIM, 1);

    // 2) gemm1: QKV, fused epilogue (fine 128x64 tiles)
    gemm_n64_qkv<<<dim3(3 * E_DIM / 64, M / 128), 128, G1_SMEM>>>(a2, w2, qd, kd, vd);

    // 3) attention -> E' [Eh|El] (into g_a2)
    attn_f16<<<dim3(8, 16, 2), 256, ATT_SMEM>>>(qd, kd, vd, a2);

    // 4) split W0, gemm2 -> fp32 out
    split2_kernel<<<(E_DIM * E_DIM / 4 + 255) / 256, 256>>>(w0, w2, E_DIM, E_DIM, 1);
    gemm_mma<<<dim3(E_DIM / BN, M / BM), 256, GEMM_SMEM>>>(
        a2, w2, out, M, E_DIM, K2);
}

// round 15
// speedup vs baseline: 3.1218x; 1.2427x over previous
#include <cuda_runtime.h>
#include <cuda_fp16.h>
#include <cstdint>
#include <cstddef>

// ---------------------------------------------------------------------------
// MHA: B=2, S=2048, E=1024, H=16, D=64, fp32, causal. fp16 split-precision:
//  X -> [Xh|Xl], Wqkv -> [Wh|Wh]
//  gemm1: Q-plane CTAs use 2-term (K'=2048); K/V planes 1-term (K'=1024)
//         fused epi -> Q [qh|ql](128), K [kh](64), V [vh](64)
//  attn (BR=128, paired q-tiles, double-buffered): QK=(Qh+Ql)Kh, PV=(Ph+Pl)Vh
//         -> E hi-only [4096,1024]
//  W0 -> hi-only ; gemm2 (K=1024) -> fp32 out
// ---------------------------------------------------------------------------

#define S_LEN   2048
#define E_DIM   1024
#define K2      2048

__device__ __half g_a2[4096 * K2];            // X' [hi|lo]; later E hi-only
__device__ __half g_w2[3072 * K2];            // Wqkv' [hi|hi]; later W0 hi
__device__ __half g_q [32 * 2048 * 128];      // Q [qh|ql] per (b,h)
__device__ __half g_k [32 * 2048 * 64];       // K hi only
__device__ __half g_v [32 * 2048 * 64];       // V hi only

// ---------------------------------------------------------------------------
__device__ __forceinline__ uint32_t smem_u32(const void* p) {
    uint32_t a;
    asm("{ .reg .u64 t; cvta.to.shared.u64 t, %1; cvt.u32.u64 %0, t; }"
        : "=r"(a) : "l"(p));
    return a;
}
__device__ __forceinline__ uint32_t pkh(__half a, __half b) {
    __half2 t = __halves2half2(a, b);
    return *reinterpret_cast<uint32_t*>(&t);
}
__device__ __forceinline__ uint32_t pkhf(float a, float b) {
    return pkh(__float2half_rn(a), __float2half_rn(b));
}
__device__ __forceinline__ void ldsm4(uint32_t r[4], uint32_t addr) {
    asm volatile("ldmatrix.sync.aligned.m8n8.x4.shared.b16 {%0,%1,%2,%3}, [%4];"
                 : "=r"(r[0]), "=r"(r[1]), "=r"(r[2]), "=r"(r[3]) : "r"(addr));
}
__device__ __forceinline__ void ldsm4t(uint32_t r[4], uint32_t addr) {
    asm volatile("ldmatrix.sync.aligned.m8n8.x4.trans.shared.b16 {%0,%1,%2,%3}, [%4];"
                 : "=r"(r[0]), "=r"(r[1]), "=r"(r[2]), "=r"(r[3]) : "r"(addr));
}
__device__ __forceinline__ void mma16816(float c[4], const uint32_t a[4],
                                         uint32_t b0, uint32_t b1) {
    asm volatile("mma.sync.aligned.m16n8k16.row.col.f32.f16.f16.f32 "
                 "{%0,%1,%2,%3}, {%4,%5,%6,%7}, {%8,%9}, {%0,%1,%2,%3};"
                 : "+f"(c[0]), "+f"(c[1]), "+f"(c[2]), "+f"(c[3])
                 : "r"(a[0]), "r"(a[1]), "r"(a[2]), "r"(a[3]), "r"(b0), "r"(b1));
}
__device__ __forceinline__ void cpa16(uint32_t dst, const void* src) {
    asm volatile("cp.async.cg.shared.global [%0], [%1], 16;" :: "r"(dst), "l"(src));
}

// ---------------------------------------------------------------------------
// split2: fp32 [rows,K] -> fp16.
//   mode 0: [hi|lo] (stride 2K); mode 1: [hi|hi] (stride 2K); mode 2: hi (K)
// ---------------------------------------------------------------------------
__global__ void split2_kernel(const float* __restrict__ src,
                              __half* __restrict__ dst,
                              int rows, int K, int mode) {
    int t = blockIdx.x * blockDim.x + threadIdx.x;
    int per4 = K >> 2;
    if (t >= rows * per4) return;
    int r = t / per4, c4 = (t - r * per4) * 4;
    float4 v = ((const float4*)src)[t];

    __half h0 = __float2half_rn(v.x), h1 = __float2half_rn(v.y);
    __half h2 = __float2half_rn(v.z), h3 = __float2half_rn(v.w);
    uint2 hp = make_uint2(pkh(h0, h1), pkh(h2, h3));

    if (mode == 2) {
        *(uint2*)(dst + (size_t)r * K + c4) = hp;
        return;
    }
    __half* d0 = dst + (size_t)r * (2 * K) + c4;
    *(uint2*)(d0) = hp;
    if (mode == 1) {
        *(uint2*)(d0 + K) = hp;
    } else {
        uint2 lp = make_uint2(pkhf(v.x - __half2float(h0), v.y - __half2float(h1)),
                              pkhf(v.z - __half2float(h2), v.w - __half2float(h3)));
        *(uint2*)(d0 + K) = lp;
    }
}

extern __shared__ char sh_raw[];

#define KSTRB 144   // bytes per smem row (72 fp16, odd multiple of 16B)

// ---------------------------------------------------------------------------
// gemm1: fused QKV epilogue. 128x64 CTA tile, 128 threads, BK=64, 2-stage,
// 4 CTAs/SM. Q-plane CTAs (bn<1024): K'=2048 (Xh+Xl); K/V planes: K'=1024.
// ---------------------------------------------------------------------------
#define G1_STG ((128 + 64) * KSTRB)      // 27648
#define G1_SMEM (2 * G1_STG)             // 55296

__global__ __launch_bounds__(128, 4)
void gemm_n64_qkv(const __half* __restrict__ A,
                  const __half* __restrict__ B,
                  __half* __restrict__ Qd,
                  __half* __restrict__ Kd,
                  __half* __restrict__ Vd) {
    const uint32_t sb = smem_u32(sh_raw);
    const int tid = threadIdx.x, wid = tid >> 5, lane = tid & 31;
    const int bm = blockIdx.y * 128, bn = blockIdx.x * 64;
    const int wm = (wid >> 1) * 64, wn = (wid & 1) * 32;
    const int g = lane >> 2, tg = lane & 3;
    const int lrow = lane & 15, lcol = (lane >> 4) * 8;

    auto load_stage = [&](int s, int kk) {
        uint32_t abase = sb + (uint32_t)s * G1_STG;
        uint32_t bbase = abase + 128 * KSTRB;
#pragma unroll
        for (int i = 0; i < 12; ++i) {          // 1536 chunks over 128 threads
            int c = tid + i * 128;
            if (c < 1024) {
                int row = c >> 3, k16 = c & 7;
                cpa16(abase + row * KSTRB + k16 * 16,
                      A + (size_t)(bm + row) * K2 + kk + k16 * 8);
            } else {
                int row = (c - 1024) >> 3, k16 = c & 7;
                cpa16(bbase + row * KSTRB + k16 * 16,
                      B + (size_t)(bn + row) * K2 + kk + k16 * 8);
            }
        }
        asm volatile("cp.async.commit_group;" ::: "memory");
    };

    float acc[4][4][4];
#pragma unroll
    for (int i = 0; i < 4; ++i)
#pragma unroll
        for (int j = 0; j < 4; ++j)
#pragma unroll
            for (int e = 0; e < 4; ++e) acc[i][j][e] = 0.0f;

    // Q plane: full 2-term (K'=2048); K/V planes: hi-term only (K'=1024)
    const int NC = (bn < 1024) ? (K2 / 64) : (1024 / 64);
    load_stage(0, 0);

    for (int c = 0; c < NC; ++c) {
        asm volatile("cp.async.wait_group 0;" ::: "memory");
        __syncthreads();
        if (c + 1 < NC) load_stage((c + 1) & 1, (c + 1) * 64);

        uint32_t abase = sb + (uint32_t)(c & 1) * G1_STG;
        uint32_t bbase = abase + 128 * KSTRB;
#pragma unroll
        for (int ks = 0; ks < 4; ++ks) {
            uint32_t a[4][4];
#pragma unroll
            for (int mt = 0; mt < 4; ++mt)
                ldsm4(a[mt], abase + (wm + mt * 16 + lrow) * KSTRB + (ks * 16 + lcol) * 2);
            uint32_t bf[4][2];
#pragma unroll
            for (int nb = 0; nb < 2; ++nb) {
                uint32_t r[4];
                ldsm4(r, bbase + (wn + nb * 16 + lrow) * KSTRB + (ks * 16 + lcol) * 2);
                bf[nb * 2][0] = r[0];     bf[nb * 2][1] = r[2];
                bf[nb * 2 + 1][0] = r[1]; bf[nb * 2 + 1][1] = r[3];
            }
#pragma unroll
            for (int mt = 0; mt < 4; ++mt)
#pragma unroll
                for (int nt = 0; nt < 4; ++nt)
                    mma16816(acc[mt][nt], a[mt], bf[nt][0], bf[nt][1]);
        }
    }

    // fused QKV epilogue: Q split hi/lo; K,V hi only
#pragma unroll
    for (int nt = 0; nt < 4; ++nt) {
        int cbase = bn + wn + nt * 8 + tg * 2;
        int plane = cbase >> 10, rem = cbase & 1023;
        int h = rem >> 6, d = rem & 63;
#pragma unroll
        for (int mt = 0; mt < 4; ++mt) {
#pragma unroll
            for (int rr = 0; rr < 2; ++rr) {
                int row = bm + wm + mt * 16 + g + rr * 8;
                int b = row >> 11, s = row & 2047;
                size_t bhs = (size_t)(b * 16 + h) * 2048 + s;
                float v0 = acc[mt][nt][rr * 2], v1 = acc[mt][nt][rr * 2 + 1];
                __half h0 = __float2half_rn(v0), h1 = __float2half_rn(v1);
                uint32_t hi = pkh(h0, h1);
                if (plane == 0) {
                    uint32_t lo = pkhf(v0 - __half2float(h0), v1 - __half2float(h1));
                    __half* p = Qd + bhs * 128 + d;
                    *(uint32_t*)(p)      = hi;
                    *(uint32_t*)(p + 64) = lo;
                } else if (plane == 1) {
                    *(uint32_t*)(Kd + bhs * 64 + d) = hi;
                } else {
                    *(uint32_t*)(Vd + bhs * 64 + d) = hi;
                }
            }
        }
    }
}

// ---------------------------------------------------------------------------
// gemm2: C = A[M,K] @ B[N,K]^T, fp32 out. 128x128 tile, 3-stage. K=1024.
// ---------------------------------------------------------------------------
#define BM 128
#define BN 128
#define BK 64
#define STG_BYTES ((BM + BN) * KSTRB)   // 36864
#define GEMM_SMEM (3 * STG_BYTES)       // 110592

__global__ __launch_bounds__(256, 2)
void gemm_mma(const __half* __restrict__ A,
              const __half* __restrict__ B,
              float* __restrict__ C, int M, int N, int K) {
    const uint32_t sb = smem_u32(sh_raw);
    const int tid = threadIdx.x, wid = tid >> 5, lane = tid & 31;
    const int bm = blockIdx.y * BM, bn = blockIdx.x * BN;
    const int wm = (wid >> 2) * 64, wn = (wid & 3) * 32;
    const int g = lane >> 2, tg = lane & 3;
    const int lrow = lane & 15, lcol = (lane >> 4) * 8;

    auto load_stage = [&](int s, int kk) {
        uint32_t abase = sb + (uint32_t)s * STG_BYTES;
        uint32_t bbase = abase + BM * KSTRB;
#pragma unroll
        for (int i = 0; i < 8; ++i) {
            int c = tid + i * 256;
            if (c < 1024) {
                int row = c >> 3, k16 = c & 7;
                cpa16(abase + row * KSTRB + k16 * 16,
                      A + (size_t)(bm + row) * K + kk + k16 * 8);
            } else {
                int row = (c - 1024) >> 3, k16 = c & 7;
                cpa16(bbase + row * KSTRB + k16 * 16,
                      B + (size_t)(bn + row) * K + kk + k16 * 8);
            }
        }
        asm volatile("cp.async.commit_group;" ::: "memory");
    };

    float acc[4][4][4];
#pragma unroll
    for (int i = 0; i < 4; ++i)
#pragma unroll
        for (int j = 0; j < 4; ++j)
#pragma unroll
            for (int e = 0; e < 4; ++e) acc[i][j][e] = 0.0f;

    const int NC = K / BK;
    load_stage(0, 0);
    load_stage(1, BK);

    int st = 0;
    for (int c = 0; c < NC; ++c) {
        if (c + 1 < NC) asm volatile("cp.async.wait_group 1;" ::: "memory");
        else            asm volatile("cp.async.wait_group 0;" ::: "memory");
        __syncthreads();
        if (c + 2 < NC) {
            int ns = st + 2; if (ns >= 3) ns -= 3;
            load_stage(ns, (c + 2) * BK);
        }

        uint32_t abase = sb + (uint32_t)st * STG_BYTES;
        uint32_t bbase = abase + BM * KSTRB;
#pragma unroll
        for (int ks = 0; ks < 4; ++ks) {
            uint32_t a[4][4];
#pragma unroll
            for (int mt = 0; mt < 4; ++mt)
                ldsm4(a[mt], abase + (wm + mt * 16 + lrow) * KSTRB + (ks * 16 + lcol) * 2);
            uint32_t bf[4][2];
#pragma unroll
            for (int nb = 0; nb < 2; ++nb) {
                uint32_t r[4];
                ldsm4(r, bbase + (wn + nb * 16 + lrow) * KSTRB + (ks * 16 + lcol) * 2);
                bf[nb * 2][0] = r[0];     bf[nb * 2][1] = r[2];
                bf[nb * 2 + 1][0] = r[1]; bf[nb * 2 + 1][1] = r[3];
            }
#pragma unroll
            for (int mt = 0; mt < 4; ++mt)
#pragma unroll
                for (int nt = 0; nt < 4; ++nt)
                    mma16816(acc[mt][nt], a[mt], bf[nt][0], bf[nt][1]);
        }
        ++st; if (st >= 3) st = 0;
    }

#pragma unroll
    for (int mt = 0; mt < 4; ++mt) {
        int r0 = bm + wm + mt * 16 + g;
#pragma unroll
        for (int nt = 0; nt < 4; ++nt) {
            int col = bn + wn + nt * 8 + tg * 2;
            *(float2*)(C + (size_t)r0 * N + col) =
                make_float2(acc[mt][nt][0], acc[mt][nt][1]);
            *(float2*)(C + (size_t)(r0 + 8) * N + col) =
                make_float2(acc[mt][nt][2], acc[mt][nt][3]);
        }
    }
}

// ---------------------------------------------------------------------------
// Flash attention fp16-2-term: BR=128, BC=64, 256 thr, paired q-tiles,
// double-buffered K/V. QK=(Qh+Ql)Kh ; PV=(Ph+Pl)Vh. E -> hi-only [4096,1024].
// ---------------------------------------------------------------------------
#define QSTR 136
#define KSTR 72
#define Q_EL  (128 * QSTR)
#define KV_EL (64 * KSTR)
#define ATT_SMEM ((Q_EL + 4 * KV_EL) * 2)   // 71680

__global__ __launch_bounds__(256, 2)
void attn_f16(const __half* __restrict__ Qg,
              const __half* __restrict__ Kg,
              const __half* __restrict__ Vg,
              __half* __restrict__ Eo) {
    const uint32_t sbQ = smem_u32(sh_raw);

    const int tid = threadIdx.x, wid = tid >> 5, lane = tid & 31;
    const int h = blockIdx.y, b = blockIdx.z;
    const size_t bh = (size_t)(b * 16 + h);
    const int g = lane >> 2, tg = lane & 3;
    const int lrow = lane & 15, lcol = (lane >> 4) * 8;
    const float scale = 0.125f * 1.44269504089f;

    auto load_kv = [&](int buf, int k0) {
        uint32_t kb = sbQ + (Q_EL + buf * 2 * KV_EL) * 2;
        uint32_t vb = kb + KV_EL * 2;
        const __half* kg = Kg + (bh * 2048 + k0) * 64;
        const __half* vg = Vg + (bh * 2048 + k0) * 64;
#pragma unroll
        for (int i = 0; i < 2; ++i) {
            int c = tid + i * 256;
            int row = c >> 3, cg = c & 7;
            cpa16(kb + (row * KSTR + cg * 8) * 2, kg + row * 64 + cg * 8);
            cpa16(vb + (row * KSTR + cg * 8) * 2, vg + row * 64 + cg * 8);
        }
        asm volatile("cp.async.commit_group;" ::: "memory");
    };

#pragma unroll 1
    for (int ph = 0; ph < 2; ++ph) {
        const int qi = ph ? (int)blockIdx.x : 15 - (int)blockIdx.x;
        const int q0 = qi * 128;
        const int ntiles = 2 * qi + 2;
        const int rowg0 = q0 + wid * 16 + g, rowg1 = rowg0 + 8;

        {
            const __half* qg = Qg + (bh * 2048 + q0) * 128;
#pragma unroll
            for (int i = 0; i < 8; ++i) {
                int c = tid + i * 256;
                int row = c >> 4, cg = c & 15;
                cpa16(sbQ + (row * QSTR + cg * 8) * 2, qg + row * 128 + cg * 8);
            }
            asm volatile("cp.async.commit_group;" ::: "memory");
        }
        load_kv(0, 0);

        float m0 = -1e30f, m1 = -1e30f, l0 = 0.0f, l1 = 0.0f;
        float o[8][4];
#pragma unroll
        for (int i = 0; i < 8; ++i)
#pragma unroll
            for (int j = 0; j < 4; ++j) o[i][j] = 0.0f;

        for (int t = 0; t < ntiles; ++t) {
            const int k0 = t * 64;
            asm volatile("cp.async.wait_group 0;" ::: "memory");
            __syncthreads();
            if (t + 1 < ntiles) load_kv((t + 1) & 1, (t + 1) * 64);

            const uint32_t kbase = sbQ + (Q_EL + (t & 1) * 2 * KV_EL) * 2;
            const uint32_t vbase = kbase + KV_EL * 2;

            // ---- S = (Qh + Ql) * Kh^T
            float s[8][4];
#pragma unroll
            for (int i = 0; i < 8; ++i)
#pragma unroll
                for (int j = 0; j < 4; ++j) s[i][j] = 0.0f;

#pragma unroll
            for (int i = 0; i < 4; ++i) {
                uint32_t qa0[4], qa1[4];
                ldsm4(qa0, sbQ + ((wid * 16 + lrow) * QSTR + i * 16 + lcol) * 2);
                ldsm4(qa1, sbQ + ((wid * 16 + lrow) * QSTR + 64 + i * 16 + lcol) * 2);
#pragma unroll
                for (int nb = 0; nb < 4; ++nb) {
                    uint32_t r0[4];
                    ldsm4(r0, kbase + ((nb * 16 + lrow) * KSTR + i * 16 + lcol) * 2);
                    mma16816(s[nb * 2],     qa0, r0[0], r0[2]);
                    mma16816(s[nb * 2 + 1], qa0, r0[1], r0[3]);
                    mma16816(s[nb * 2],     qa1, r0[0], r0[2]);
                    mma16816(s[nb * 2 + 1], qa1, r0[1], r0[3]);
                }
            }

            if (t >= ntiles - 2) {
#pragma unroll
                for (int nt = 0; nt < 8; ++nt)
#pragma unroll
                    for (int ee = 0; ee < 4; ++ee) {
                        int col = k0 + nt * 8 + tg * 2 + (ee & 1);
                        int row = (ee < 2) ? rowg0 : rowg1;
                        if (col > row) s[nt][ee] = -1e30f;
                        else           s[nt][ee] *= scale;
                    }
            } else {
#pragma unroll
                for (int nt = 0; nt < 8; ++nt)
#pragma unroll
                    for (int ee = 0; ee < 4; ++ee) s[nt][ee] *= scale;
            }

            float rmax0 = -1e30f, rmax1 = -1e30f;
#pragma unroll
            for (int nt = 0; nt < 8; ++nt) {
                rmax0 = fmaxf(rmax0, fmaxf(s[nt][0], s[nt][1]));
                rmax1 = fmaxf(rmax1, fmaxf(s[nt][2], s[nt][3]));
            }
            rmax0 = fmaxf(rmax0, __shfl_xor_sync(0xffffffffu, rmax0, 1));
            rmax0 = fmaxf(rmax0, __shfl_xor_sync(0xffffffffu, rmax0, 2));
            rmax1 = fmaxf(rmax1, __shfl_xor_sync(0xffffffffu, rmax1, 1));
            rmax1 = fmaxf(rmax1, __shfl_xor_sync(0xffffffffu, rmax1, 2));

            float mn0 = fmaxf(m0, rmax0), mn1 = fmaxf(m1, rmax1);
            float al0 = exp2f(m0 - mn0), al1 = exp2f(m1 - mn1);
            m0 = mn0; m1 = mn1;

            float rs0 = 0.0f, rs1 = 0.0f;
#pragma unroll
            for (int nt = 0; nt < 8; ++nt) {
                s[nt][0] = exp2f(s[nt][0] - m0);
                s[nt][1] = exp2f(s[nt][1] - m0);
                s[nt][2] = exp2f(s[nt][2] - m1);
                s[nt][3] = exp2f(s[nt][3] - m1);
                rs0 += s[nt][0] + s[nt][1];
                rs1 += s[nt][2] + s[nt][3];
            }
            rs0 += __shfl_xor_sync(0xffffffffu, rs0, 1);
            rs0 += __shfl_xor_sync(0xffffffffu, rs0, 2);
            rs1 += __shfl_xor_sync(0xffffffffu, rs1, 1);
            rs1 += __shfl_xor_sync(0xffffffffu, rs1, 2);
            l0 = l0 * al0 + rs0;
            l1 = l1 * al1 + rs1;
#pragma unroll
            for (int nt = 0; nt < 8; ++nt) {
                o[nt][0] *= al0; o[nt][1] *= al0;
                o[nt][2] *= al1; o[nt][3] *= al1;
            }

            uint32_t pfh[4][4], pfl[4][4];
#pragma unroll
            for (int kc = 0; kc < 4; ++kc) {
                const float* se = s[kc * 2];
                const float* so = s[kc * 2 + 1];
                __half he0 = __float2half_rn(se[0]), he1 = __float2half_rn(se[1]);
                __half he2 = __float2half_rn(se[2]), he3 = __float2half_rn(se[3]);
                __half ho0 = __float2half_rn(so[0]), ho1 = __float2half_rn(so[1]);
                __half ho2 = __float2half_rn(so[2]), ho3 = __float2half_rn(so[3]);
                pfh[kc][0] = pkh(he0, he1); pfh[kc][1] = pkh(he2, he3);
                pfh[kc][2] = pkh(ho0, ho1); pfh[kc][3] = pkh(ho2, ho3);
                pfl[kc][0] = pkhf(se[0] - __half2float(he0), se[1] - __half2float(he1));
                pfl[kc][1] = pkhf(se[2] - __half2float(he2), se[3] - __half2float(he3));
                pfl[kc][2] = pkhf(so[0] - __half2float(ho0), so[1] - __half2float(ho1));
                pfl[kc][3] = pkhf(so[2] - __half2float(ho2), so[3] - __half2float(ho3));
            }

#pragma unroll
            for (int kc = 0; kc < 4; ++kc) {
#pragma unroll
                for (int db = 0; db < 4; ++db) {
                    uint32_t rh[4];
                    ldsm4t(rh, vbase + ((kc * 16 + lrow) * KSTR + db * 16 + lcol) * 2);
                    mma16816(o[db * 2],     pfh[kc], rh[0], rh[1]);
                    mma16816(o[db * 2 + 1], pfh[kc], rh[2], rh[3]);
                    mma16816(o[db * 2],     pfl[kc], rh[0], rh[1]);
                    mma16816(o[db * 2 + 1], pfl[kc], rh[2], rh[3]);
                }
            }
        }

        // ---- epilogue: write E hi-only to Eo [4096, 1024]
        float inv0 = 1.0f / l0, inv1 = 1.0f / l1;
        size_t r0 = (size_t)(b * 2048) + rowg0;
        size_t r1 = (size_t)(b * 2048) + rowg1;
#pragma unroll
        for (int nt = 0; nt < 8; ++nt) {
            int col = h * 64 + nt * 8 + tg * 2;
            *(uint32_t*)(Eo + r0 * E_DIM + col) =
                pkhf(o[nt][0] * inv0, o[nt][1] * inv0);
            *(uint32_t*)(Eo + r1 * E_DIM + col) =
                pkhf(o[nt][2] * inv1, o[nt][3] * inv1);
        }

        __syncthreads();   // protect Q/K/V smem before next phase
    }
}

// ---------------------------------------------------------------------------
// launch
// ---------------------------------------------------------------------------
extern "C" void kernel_launch(void* const* d_in, const int* in_sizes, int n_in,
                              void* d_out, int out_size) {
    (void)in_sizes; (void)n_in; (void)out_size;
    const float* x    = (const float*)d_in[0];
    const float* wqkv = (const float*)d_in[1];
    const float* w0   = (const float*)d_in[2];
    float* out = (float*)d_out;

    __half *a2, *w2, *qd, *kd, *vd;
    cudaGetSymbolAddress((void**)&a2, g_a2);
    cudaGetSymbolAddress((void**)&w2, g_w2);
    cudaGetSymbolAddress((void**)&qd, g_q);
    cudaGetSymbolAddress((void**)&kd, g_k);
    cudaGetSymbolAddress((void**)&vd, g_v);

    cudaFuncSetAttribute(gemm_n64_qkv,
                         cudaFuncAttributeMaxDynamicSharedMemorySize, G1_SMEM);
    cudaFuncSetAttribute(gemm_mma,
                         cudaFuncAttributeMaxDynamicSharedMemorySize, GEMM_SMEM);
    cudaFuncSetAttribute(attn_f16,
                         cudaFuncAttributeMaxDynamicSharedMemorySize, ATT_SMEM);

    const int M = 4096;

    // 1) splits: X -> [Xh|Xl]; Wqkv -> [Wh|Wh]
    split2_kernel<<<(M * E_DIM / 4 + 255) / 256, 256>>>(x, a2, M, E_DIM, 0);
    split2_kernel<<<(3 * E_DIM * E_DIM / 4 + 255) / 256, 256>>>(wqkv, w2, 3 * E_DIM, E_DIM, 1);

    // 2) gemm1: QKV fused epilogue (Q-plane 2-term, K/V 1-term)
    gemm_n64_qkv<<<dim3(3 * E_DIM / 64, M / 128), 128, G1_SMEM>>>(a2, w2, qd, kd, vd);

    // 3) attention -> E hi-only (into g_a2, [4096,1024])
    attn_f16<<<dim3(8, 16, 2), 256, ATT_SMEM>>>(qd, kd, vd, a2);

    // 4) W0 -> hi-only [1024,1024]; gemm2 (K=1024) -> fp32 out
    split2_kernel<<<(E_DIM * E_DIM / 4 + 255) / 256, 256>>>(w0, w2, E_DIM, E_DIM, 2);
    gemm_mma<<<dim3(E_DIM / BN, M / BM), 256, GEMM_SMEM>>>(
        a2, w2, out, M, E_DIM, E_DIM);
}

// round 17
// speedup vs baseline: 3.3987x; 1.0887x over previous
#include <cuda_runtime.h>
#include <cuda_fp16.h>
#include <cstdint>
#include <cstddef>

// ---------------------------------------------------------------------------
// MHA: B=2, S=2048, E=1024, H=16, D=64, fp32, causal. fp16 split-precision:
//  X -> [Xh|Xl] (2048); Wqkv -> hi-only (1024, B-loads wrap)
//  gemm1: Q-plane 2-term (K'=2048), K/V planes 1-term; fused epi ->
//         Q [qh|ql](128), K [kh](64), V [vh](64)
//  attn: QK=(Qh+Ql)Kh (2-term), PV=Ph*Vh (1-term) -> E hi-only [4096,1024]
//  W0 hi-only ; gemm2 (K=1024) -> fp32 out
// ---------------------------------------------------------------------------

#define S_LEN   2048
#define E_DIM   1024
#define K2      2048

__device__ __half g_a2[4096 * K2];            // X' [hi|lo]; later E hi-only
__device__ __half g_w2[3072 * E_DIM];         // Wqkv hi; later W0 hi
__device__ __half g_q [32 * 2048 * 128];      // Q [qh|ql] per (b,h)
__device__ __half g_k [32 * 2048 * 64];       // K hi only
__device__ __half g_v [32 * 2048 * 64];       // V hi only

// ---------------------------------------------------------------------------
__device__ __forceinline__ uint32_t smem_u32(const void* p) {
    uint32_t a;
    asm("{ .reg .u64 t; cvta.to.shared.u64 t, %1; cvt.u32.u64 %0, t; }"
        : "=r"(a) : "l"(p));
    return a;
}
__device__ __forceinline__ uint32_t pkh(__half a, __half b) {
    __half2 t = __halves2half2(a, b);
    return *reinterpret_cast<uint32_t*>(&t);
}
__device__ __forceinline__ uint32_t pkhf(float a, float b) {
    return pkh(__float2half_rn(a), __float2half_rn(b));
}
__device__ __forceinline__ void ldsm4(uint32_t r[4], uint32_t addr) {
    asm volatile("ldmatrix.sync.aligned.m8n8.x4.shared.b16 {%0,%1,%2,%3}, [%4];"
                 : "=r"(r[0]), "=r"(r[1]), "=r"(r[2]), "=r"(r[3]) : "r"(addr));
}
__device__ __forceinline__ void ldsm4t(uint32_t r[4], uint32_t addr) {
    asm volatile("ldmatrix.sync.aligned.m8n8.x4.trans.shared.b16 {%0,%1,%2,%3}, [%4];"
                 : "=r"(r[0]), "=r"(r[1]), "=r"(r[2]), "=r"(r[3]) : "r"(addr));
}
__device__ __forceinline__ void mma16816(float c[4], const uint32_t a[4],
                                         uint32_t b0, uint32_t b1) {
    asm volatile("mma.sync.aligned.m16n8k16.row.col.f32.f16.f16.f32 "
                 "{%0,%1,%2,%3}, {%4,%5,%6,%7}, {%8,%9}, {%0,%1,%2,%3};"
                 : "+f"(c[0]), "+f"(c[1]), "+f"(c[2]), "+f"(c[3])
                 : "r"(a[0]), "r"(a[1]), "r"(a[2]), "r"(a[3]), "r"(b0), "r"(b1));
}
__device__ __forceinline__ void cpa16(uint32_t dst, const void* src) {
    asm volatile("cp.async.cg.shared.global [%0], [%1], 16;" :: "r"(dst), "l"(src));
}

// ---------------------------------------------------------------------------
// split2: fp32 [rows,K] -> fp16. mode 0: [hi|lo] (stride 2K); mode 2: hi (K)
// ---------------------------------------------------------------------------
__global__ void split2_kernel(const float* __restrict__ src,
                              __half* __restrict__ dst,
                              int rows, int K, int mode) {
    int t = blockIdx.x * blockDim.x + threadIdx.x;
    int per4 = K >> 2;
    if (t >= rows * per4) return;
    int r = t / per4, c4 = (t - r * per4) * 4;
    float4 v = ((const float4*)src)[t];

    __half h0 = __float2half_rn(v.x), h1 = __float2half_rn(v.y);
    __half h2 = __float2half_rn(v.z), h3 = __float2half_rn(v.w);
    uint2 hp = make_uint2(pkh(h0, h1), pkh(h2, h3));

    if (mode == 2) {
        *(uint2*)(dst + (size_t)r * K + c4) = hp;
        return;
    }
    __half* d0 = dst + (size_t)r * (2 * K) + c4;
    *(uint2*)(d0) = hp;
    uint2 lp = make_uint2(pkhf(v.x - __half2float(h0), v.y - __half2float(h1)),
                          pkhf(v.z - __half2float(h2), v.w - __half2float(h3)));
    *(uint2*)(d0 + K) = lp;
}

extern __shared__ char sh_raw[];

#define KSTRB 144   // bytes per smem row (72 fp16, odd multiple of 16B)

// ---------------------------------------------------------------------------
// gemm1: fused QKV epilogue. 128x64 CTA tile, 128 threads, BK=64, 2-stage,
// 4 CTAs/SM. Q-plane (bn<1024): K'=2048 over [Xh|Xl] with B wrapping into
// the hi-only weight block; K/V planes: K'=1024.
// ---------------------------------------------------------------------------
#define G1_STG ((128 + 64) * KSTRB)      // 27648
#define G1_SMEM (2 * G1_STG)             // 55296

__global__ __launch_bounds__(128, 4)
void gemm_n64_qkv(const __half* __restrict__ A,
                  const __half* __restrict__ B,
                  __half* __restrict__ Qd,
                  __half* __restrict__ Kd,
                  __half* __restrict__ Vd) {
    const uint32_t sb = smem_u32(sh_raw);
    const int tid = threadIdx.x, wid = tid >> 5, lane = tid & 31;
    const int bm = blockIdx.y * 128, bn = blockIdx.x * 64;
    const int wm = (wid >> 1) * 64, wn = (wid & 1) * 32;
    const int g = lane >> 2, tg = lane & 3;
    const int lrow = lane & 15, lcol = (lane >> 4) * 8;

    auto load_stage = [&](int s, int kk) {
        uint32_t abase = sb + (uint32_t)s * G1_STG;
        uint32_t bbase = abase + 128 * KSTRB;
        const int bkk = kk & 1023;          // weights stored hi-only (1024)
#pragma unroll
        for (int i = 0; i < 12; ++i) {      // 1536 chunks over 128 threads
            int c = tid + i * 128;
            if (c < 1024) {
                int row = c >> 3, k16 = c & 7;
                cpa16(abase + row * KSTRB + k16 * 16,
                      A + (size_t)(bm + row) * K2 + kk + k16 * 8);
            } else {
                int row = (c - 1024) >> 3, k16 = c & 7;
                cpa16(bbase + row * KSTRB + k16 * 16,
                      B + (size_t)(bn + row) * E_DIM + bkk + k16 * 8);
            }
        }
        asm volatile("cp.async.commit_group;" ::: "memory");
    };

    float acc[4][4][4];
#pragma unroll
    for (int i = 0; i < 4; ++i)
#pragma unroll
        for (int j = 0; j < 4; ++j)
#pragma unroll
            for (int e = 0; e < 4; ++e) acc[i][j][e] = 0.0f;

    // Q plane: full 2-term (K'=2048); K/V planes: hi-term only (K'=1024)
    const int NC = (bn < 1024) ? (K2 / 64) : (1024 / 64);
    load_stage(0, 0);

    for (int c = 0; c < NC; ++c) {
        asm volatile("cp.async.wait_group 0;" ::: "memory");
        __syncthreads();
        if (c + 1 < NC) load_stage((c + 1) & 1, (c + 1) * 64);

        uint32_t abase = sb + (uint32_t)(c & 1) * G1_STG;
        uint32_t bbase = abase + 128 * KSTRB;
#pragma unroll
        for (int ks = 0; ks < 4; ++ks) {
            uint32_t a[4][4];
#pragma unroll
            for (int mt = 0; mt < 4; ++mt)
                ldsm4(a[mt], abase + (wm + mt * 16 + lrow) * KSTRB + (ks * 16 + lcol) * 2);
            uint32_t bf[4][2];
#pragma unroll
            for (int nb = 0; nb < 2; ++nb) {
                uint32_t r[4];
                ldsm4(r, bbase + (wn + nb * 16 + lrow) * KSTRB + (ks * 16 + lcol) * 2);
                bf[nb * 2][0] = r[0];     bf[nb * 2][1] = r[2];
                bf[nb * 2 + 1][0] = r[1]; bf[nb * 2 + 1][1] = r[3];
            }
#pragma unroll
            for (int mt = 0; mt < 4; ++mt)
#pragma unroll
                for (int nt = 0; nt < 4; ++nt)
                    mma16816(acc[mt][nt], a[mt], bf[nt][0], bf[nt][1]);
        }
    }

    // fused QKV epilogue: Q split hi/lo; K,V hi only
#pragma unroll
    for (int nt = 0; nt < 4; ++nt) {
        int cbase = bn + wn + nt * 8 + tg * 2;
        int plane = cbase >> 10, rem = cbase & 1023;
        int h = rem >> 6, d = rem & 63;
#pragma unroll
        for (int mt = 0; mt < 4; ++mt) {
#pragma unroll
            for (int rr = 0; rr < 2; ++rr) {
                int row = bm + wm + mt * 16 + g + rr * 8;
                int b = row >> 11, s = row & 2047;
                size_t bhs = (size_t)(b * 16 + h) * 2048 + s;
                float v0 = acc[mt][nt][rr * 2], v1 = acc[mt][nt][rr * 2 + 1];
                __half h0 = __float2half_rn(v0), h1 = __float2half_rn(v1);
                uint32_t hi = pkh(h0, h1);
                if (plane == 0) {
                    uint32_t lo = pkhf(v0 - __half2float(h0), v1 - __half2float(h1));
                    __half* p = Qd + bhs * 128 + d;
                    *(uint32_t*)(p)      = hi;
                    *(uint32_t*)(p + 64) = lo;
                } else if (plane == 1) {
                    *(uint32_t*)(Kd + bhs * 64 + d) = hi;
                } else {
                    *(uint32_t*)(Vd + bhs * 64 + d) = hi;
                }
            }
        }
    }
}

// ---------------------------------------------------------------------------
// gemm2: C = A[M,K] @ B[N,K]^T, fp32 out. 128x128 tile, 3-stage. K=1024.
// ---------------------------------------------------------------------------
#define BM 128
#define BN 128
#define BK 64
#define STG_BYTES ((BM + BN) * KSTRB)   // 36864
#define GEMM_SMEM (3 * STG_BYTES)       // 110592

__global__ __launch_bounds__(256, 2)
void gemm_mma(const __half* __restrict__ A,
              const __half* __restrict__ B,
              float* __restrict__ C, int M, int N, int K) {
    const uint32_t sb = smem_u32(sh_raw);
    const int tid = threadIdx.x, wid = tid >> 5, lane = tid & 31;
    const int bm = blockIdx.y * BM, bn = blockIdx.x * BN;
    const int wm = (wid >> 2) * 64, wn = (wid & 3) * 32;
    const int g = lane >> 2, tg = lane & 3;
    const int lrow = lane & 15, lcol = (lane >> 4) * 8;

    auto load_stage = [&](int s, int kk) {
        uint32_t abase = sb + (uint32_t)s * STG_BYTES;
        uint32_t bbase = abase + BM * KSTRB;
#pragma unroll
        for (int i = 0; i < 8; ++i) {
            int c = tid + i * 256;
            if (c < 1024) {
                int row = c >> 3, k16 = c & 7;
                cpa16(abase + row * KSTRB + k16 * 16,
                      A + (size_t)(bm + row) * K + kk + k16 * 8);
            } else {
                int row = (c - 1024) >> 3, k16 = c & 7;
                cpa16(bbase + row * KSTRB + k16 * 16,
                      B + (size_t)(bn + row) * K + kk + k16 * 8);
            }
        }
        asm volatile("cp.async.commit_group;" ::: "memory");
    };

    float acc[4][4][4];
#pragma unroll
    for (int i = 0; i < 4; ++i)
#pragma unroll
        for (int j = 0; j < 4; ++j)
#pragma unroll
            for (int e = 0; e < 4; ++e) acc[i][j][e] = 0.0f;

    const int NC = K / BK;
    load_stage(0, 0);
    load_stage(1, BK);

    int st = 0;
    for (int c = 0; c < NC; ++c) {
        if (c + 1 < NC) asm volatile("cp.async.wait_group 1;" ::: "memory");
        else            asm volatile("cp.async.wait_group 0;" ::: "memory");
        __syncthreads();
        if (c + 2 < NC) {
            int ns = st + 2; if (ns >= 3) ns -= 3;
            load_stage(ns, (c + 2) * BK);
        }

        uint32_t abase = sb + (uint32_t)st * STG_BYTES;
        uint32_t bbase = abase + BM * KSTRB;
#pragma unroll
        for (int ks = 0; ks < 4; ++ks) {
            uint32_t a[4][4];
#pragma unroll
            for (int mt = 0; mt < 4; ++mt)
                ldsm4(a[mt], abase + (wm + mt * 16 + lrow) * KSTRB + (ks * 16 + lcol) * 2);
            uint32_t bf[4][2];
#pragma unroll
            for (int nb = 0; nb < 2; ++nb) {
                uint32_t r[4];
                ldsm4(r, bbase + (wn + nb * 16 + lrow) * KSTRB + (ks * 16 + lcol) * 2);
                bf[nb * 2][0] = r[0];     bf[nb * 2][1] = r[2];
                bf[nb * 2 + 1][0] = r[1]; bf[nb * 2 + 1][1] = r[3];
            }
#pragma unroll
            for (int mt = 0; mt < 4; ++mt)
#pragma unroll
                for (int nt = 0; nt < 4; ++nt)
                    mma16816(acc[mt][nt], a[mt], bf[nt][0], bf[nt][1]);
        }
        ++st; if (st >= 3) st = 0;
    }

#pragma unroll
    for (int mt = 0; mt < 4; ++mt) {
        int r0 = bm + wm + mt * 16 + g;
#pragma unroll
        for (int nt = 0; nt < 4; ++nt) {
            int col = bn + wn + nt * 8 + tg * 2;
            *(float2*)(C + (size_t)r0 * N + col) =
                make_float2(acc[mt][nt][0], acc[mt][nt][1]);
            *(float2*)(C + (size_t)(r0 + 8) * N + col) =
                make_float2(acc[mt][nt][2], acc[mt][nt][3]);
        }
    }
}

// ---------------------------------------------------------------------------
// Flash attention: BR=128, BC=64, 256 thr, paired q-tiles, double-buffered
// K/V. QK=(Qh+Ql)Kh (2-term); PV=Ph*Vh (1-term). E -> hi-only [4096,1024].
// ---------------------------------------------------------------------------
#define QSTR 136
#define KSTR 72
#define Q_EL  (128 * QSTR)
#define KV_EL (64 * KSTR)
#define ATT_SMEM ((Q_EL + 4 * KV_EL) * 2)   // 71680

__global__ __launch_bounds__(256, 2)
void attn_f16(const __half* __restrict__ Qg,
              const __half* __restrict__ Kg,
              const __half* __restrict__ Vg,
              __half* __restrict__ Eo) {
    const uint32_t sbQ = smem_u32(sh_raw);

    const int tid = threadIdx.x, wid = tid >> 5, lane = tid & 31;
    const int h = blockIdx.y, b = blockIdx.z;
    const size_t bh = (size_t)(b * 16 + h);
    const int g = lane >> 2, tg = lane & 3;
    const int lrow = lane & 15, lcol = (lane >> 4) * 8;
    const float scale = 0.125f * 1.44269504089f;

    auto load_kv = [&](int buf, int k0) {
        uint32_t kb = sbQ + (Q_EL + buf * 2 * KV_EL) * 2;
        uint32_t vb = kb + KV_EL * 2;
        const __half* kg = Kg + (bh * 2048 + k0) * 64;
        const __half* vg = Vg + (bh * 2048 + k0) * 64;
#pragma unroll
        for (int i = 0; i < 2; ++i) {
            int c = tid + i * 256;
            int row = c >> 3, cg = c & 7;
            cpa16(kb + (row * KSTR + cg * 8) * 2, kg + row * 64 + cg * 8);
            cpa16(vb + (row * KSTR + cg * 8) * 2, vg + row * 64 + cg * 8);
        }
        asm volatile("cp.async.commit_group;" ::: "memory");
    };

#pragma unroll 1
    for (int ph = 0; ph < 2; ++ph) {
        const int qi = ph ? (int)blockIdx.x : 15 - (int)blockIdx.x;
        const int q0 = qi * 128;
        const int ntiles = 2 * qi + 2;
        const int rowg0 = q0 + wid * 16 + g, rowg1 = rowg0 + 8;

        {
            const __half* qg = Qg + (bh * 2048 + q0) * 128;
#pragma unroll
            for (int i = 0; i < 8; ++i) {
                int c = tid + i * 256;
                int row = c >> 4, cg = c & 15;
                cpa16(sbQ + (row * QSTR + cg * 8) * 2, qg + row * 128 + cg * 8);
            }
            asm volatile("cp.async.commit_group;" ::: "memory");
        }
        load_kv(0, 0);

        float m0 = -1e30f, m1 = -1e30f, l0 = 0.0f, l1 = 0.0f;
        float o[8][4];
#pragma unroll
        for (int i = 0; i < 8; ++i)
#pragma unroll
            for (int j = 0; j < 4; ++j) o[i][j] = 0.0f;

        for (int t = 0; t < ntiles; ++t) {
            const int k0 = t * 64;
            asm volatile("cp.async.wait_group 0;" ::: "memory");
            __syncthreads();
            if (t + 1 < ntiles) load_kv((t + 1) & 1, (t + 1) * 64);

            const uint32_t kbase = sbQ + (Q_EL + (t & 1) * 2 * KV_EL) * 2;
            const uint32_t vbase = kbase + KV_EL * 2;

            // ---- S = (Qh + Ql) * Kh^T
            float s[8][4];
#pragma unroll
            for (int i = 0; i < 8; ++i)
#pragma unroll
                for (int j = 0; j < 4; ++j) s[i][j] = 0.0f;

#pragma unroll
            for (int i = 0; i < 4; ++i) {
                uint32_t qa0[4], qa1[4];
                ldsm4(qa0, sbQ + ((wid * 16 + lrow) * QSTR + i * 16 + lcol) * 2);
                ldsm4(qa1, sbQ + ((wid * 16 + lrow) * QSTR + 64 + i * 16 + lcol) * 2);
#pragma unroll
                for (int nb = 0; nb < 4; ++nb) {
                    uint32_t r0[4];
                    ldsm4(r0, kbase + ((nb * 16 + lrow) * KSTR + i * 16 + lcol) * 2);
                    mma16816(s[nb * 2],     qa0, r0[0], r0[2]);
                    mma16816(s[nb * 2 + 1], qa0, r0[1], r0[3]);
                    mma16816(s[nb * 2],     qa1, r0[0], r0[2]);
                    mma16816(s[nb * 2 + 1], qa1, r0[1], r0[3]);
                }
            }

            if (t >= ntiles - 2) {
#pragma unroll
                for (int nt = 0; nt < 8; ++nt)
#pragma unroll
                    for (int ee = 0; ee < 4; ++ee) {
                        int col = k0 + nt * 8 + tg * 2 + (ee & 1);
                        int row = (ee < 2) ? rowg0 : rowg1;
                        if (col > row) s[nt][ee] = -1e30f;
                        else           s[nt][ee] *= scale;
                    }
            } else {
#pragma unroll
                for (int nt = 0; nt < 8; ++nt)
#pragma unroll
                    for (int ee = 0; ee < 4; ++ee) s[nt][ee] *= scale;
            }

            float rmax0 = -1e30f, rmax1 = -1e30f;
#pragma unroll
            for (int nt = 0; nt < 8; ++nt) {
                rmax0 = fmaxf(rmax0, fmaxf(s[nt][0], s[nt][1]));
                rmax1 = fmaxf(rmax1, fmaxf(s[nt][2], s[nt][3]));
            }
            rmax0 = fmaxf(rmax0, __shfl_xor_sync(0xffffffffu, rmax0, 1));
            rmax0 = fmaxf(rmax0, __shfl_xor_sync(0xffffffffu, rmax0, 2));
            rmax1 = fmaxf(rmax1, __shfl_xor_sync(0xffffffffu, rmax1, 1));
            rmax1 = fmaxf(rmax1, __shfl_xor_sync(0xffffffffu, rmax1, 2));

            float mn0 = fmaxf(m0, rmax0), mn1 = fmaxf(m1, rmax1);
            float al0 = exp2f(m0 - mn0), al1 = exp2f(m1 - mn1);
            m0 = mn0; m1 = mn1;

            float rs0 = 0.0f, rs1 = 0.0f;
#pragma unroll
            for (int nt = 0; nt < 8; ++nt) {
                s[nt][0] = exp2f(s[nt][0] - m0);
                s[nt][1] = exp2f(s[nt][1] - m0);
                s[nt][2] = exp2f(s[nt][2] - m1);
                s[nt][3] = exp2f(s[nt][3] - m1);
                rs0 += s[nt][0] + s[nt][1];
                rs1 += s[nt][2] + s[nt][3];
            }
            rs0 += __shfl_xor_sync(0xffffffffu, rs0, 1);
            rs0 += __shfl_xor_sync(0xffffffffu, rs0, 2);
            rs1 += __shfl_xor_sync(0xffffffffu, rs1, 1);
            rs1 += __shfl_xor_sync(0xffffffffu, rs1, 2);
            l0 = l0 * al0 + rs0;
            l1 = l1 * al1 + rs1;
#pragma unroll
            for (int nt = 0; nt < 8; ++nt) {
                o[nt][0] *= al0; o[nt][1] *= al0;
                o[nt][2] *= al1; o[nt][3] *= al1;
            }

            // ---- P -> fp16 hi A-fragments (1-term PV)
            uint32_t pfh[4][4];
#pragma unroll
            for (int kc = 0; kc < 4; ++kc) {
                const float* se = s[kc * 2];
                const float* so = s[kc * 2 + 1];
                pfh[kc][0] = pkhf(se[0], se[1]);
                pfh[kc][1] = pkhf(se[2], se[3]);
                pfh[kc][2] = pkhf(so[0], so[1]);
                pfh[kc][3] = pkhf(so[2], so[3]);
            }

            // ---- O += Ph * Vh   (V via ldmatrix.trans)
#pragma unroll
            for (int kc = 0; kc < 4; ++kc) {
#pragma unroll
                for (int db = 0; db < 4; ++db) {
                    uint32_t rh[4];
                    ldsm4t(rh, vbase + ((kc * 16 + lrow) * KSTR + db * 16 + lcol) * 2);
                    mma16816(o[db * 2],     pfh[kc], rh[0], rh[1]);
                    mma16816(o[db * 2 + 1], pfh[kc], rh[2], rh[3]);
                }
            }
        }

        // ---- epilogue: write E hi-only to Eo [4096, 1024]
        float inv0 = 1.0f / l0, inv1 = 1.0f / l1;
        size_t r0 = (size_t)(b * 2048) + rowg0;
        size_t r1 = (size_t)(b * 2048) + rowg1;
#pragma unroll
        for (int nt = 0; nt < 8; ++nt) {
            int col = h * 64 + nt * 8 + tg * 2;
            *(uint32_t*)(Eo + r0 * E_DIM + col) =
                pkhf(o[nt][0] * inv0, o[nt][1] * inv0);
            *(uint32_t*)(Eo + r1 * E_DIM + col) =
                pkhf(o[nt][2] * inv1, o[nt][3] * inv1);
        }

        __syncthreads();   // protect Q/K/V smem before next phase
    }
}

// ---------------------------------------------------------------------------
// launch
// ---------------------------------------------------------------------------
extern "C" void kernel_launch(void* const* d_in, const int* in_sizes, int n_in,
                              void* d_out, int out_size) {
    (void)in_sizes; (void)n_in; (void)out_size;
    const float* x    = (const float*)d_in[0];
    const float* wqkv = (const float*)d_in[1];
    const float* w0   = (const float*)d_in[2];
    float* out = (float*)d_out;

    __half *a2, *w2, *qd, *kd, *vd;
    cudaGetSymbolAddress((void**)&a2, g_a2);
    cudaGetSymbolAddress((void**)&w2, g_w2);
    cudaGetSymbolAddress((void**)&qd, g_q);
    cudaGetSymbolAddress((void**)&kd, g_k);
    cudaGetSymbolAddress((void**)&vd, g_v);

    cudaFuncSetAttribute(gemm_n64_qkv,
                         cudaFuncAttributeMaxDynamicSharedMemorySize, G1_SMEM);
    cudaFuncSetAttribute(gemm_mma,
                         cudaFuncAttributeMaxDynamicSharedMemorySize, GEMM_SMEM);
    cudaFuncSetAttribute(attn_f16,
                         cudaFuncAttributeMaxDynamicSharedMemorySize, ATT_SMEM);

    const int M = 4096;

    // 1) splits: X -> [Xh|Xl]; Wqkv -> hi-only
    split2_kernel<<<(M * E_DIM / 4 + 255) / 256, 256>>>(x, a2, M, E_DIM, 0);
    split2_kernel<<<(3 * E_DIM * E_DIM / 4 + 255) / 256, 256>>>(wqkv, w2, 3 * E_DIM, E_DIM, 2);

    // 2) gemm1: QKV fused epilogue (Q-plane 2-term, K/V 1-term)
    gemm_n64_qkv<<<dim3(3 * E_DIM / 64, M / 128), 128, G1_SMEM>>>(a2, w2, qd, kd, vd);

    // 3) attention -> E hi-only (into g_a2, [4096,1024])
    attn_f16<<<dim3(8, 16, 2), 256, ATT_SMEM>>>(qd, kd, vd, a2);

    // 4) W0 -> hi-only; gemm2 (K=1024) -> fp32 out
    split2_kernel<<<(E_DIM * E_DIM / 4 + 255) / 256, 256>>>(w0, w2, E_DIM, E_DIM, 2);
    gemm_mma<<<dim3(E_DIM / BN, M / BM), 256, GEMM_SMEM>>>(
        a2, w2, out, M, E_DIM, E_DIM);
}